// round 9
// baseline (speedup 1.0000x reference)
#include <cuda_runtime.h>
#include <cstdint>

// Problem constants (fixed shapes from reference setup_inputs)
#define T_STEPS 4
#define B_BATCH 32            // TB / T = 128/4
#define N_SEQ   1024
#define CIN     512
#define COUT    512
#define M_TOTAL (T_STEPS * B_BATCH * N_SEQ)   // 131072 rows

// Scratch in device globals (no allocations allowed)
__device__ float g_y[(size_t)M_TOTAL * COUT];      // 268 MB GEMM output
__device__ float g_wt[CIN][COUT];                   // W transposed: [k][o], 1 MB
#define NPART 1024
__device__ float g_psum[NPART * COUT];
__device__ float g_psq [NPART * COUT];
__device__ float g_mean[COUT];
__device__ float g_rstd[COUT];

// ---------------------------------------------------------------------------
// Packed f32x2 helpers (per-lane bitwise-identical to scalar fmaf).
// ---------------------------------------------------------------------------
__device__ __forceinline__ unsigned long long pack_dup(float a) {
    unsigned long long u;
    asm("mov.b64 %0, {%1, %1};" : "=l"(u) : "f"(a));
    return u;
}
__device__ __forceinline__ void fma2(unsigned long long& acc,
                                     unsigned long long a,
                                     unsigned long long b) {
    asm("fma.rn.f32x2 %0, %1, %2, %0;" : "+l"(acc) : "l"(a), "l"(b));
}
__device__ __forceinline__ float2 unpack2(unsigned long long u) {
    float lo, hi;
    asm("mov.b64 {%0, %1}, %2;" : "=f"(lo), "=f"(hi) : "l"(u));
    return make_float2(lo, hi);
}
__device__ __forceinline__ uint32_t smem_u32(const void* p) {
    uint32_t a;
    asm("{ .reg .u64 t; cvta.to.shared.u64 t, %1; cvt.u32.u64 %0, t; }" : "=r"(a) : "l"(p));
    return a;
}
__device__ __forceinline__ void cp_async16(uint32_t dst, const void* src) {
    asm volatile("cp.async.cg.shared.global [%0], [%1], 16;" :: "r"(dst), "l"(src) : "memory");
}

// ---------------------------------------------------------------------------
// Tiled transpose: g_wt[k][o] = W[o][k].
// ---------------------------------------------------------------------------
__global__ void __launch_bounds__(256)
wt_k(const float* __restrict__ W) {
    __shared__ float t[32][33];
    const int bo = blockIdx.x * 32;
    const int bk = blockIdx.y * 32;
    const int lx = threadIdx.x & 31;
    const int ly = threadIdx.x >> 5;
#pragma unroll
    for (int i = 0; i < 4; i++)
        t[ly + 8 * i][lx] = W[(size_t)(bo + ly + 8 * i) * CIN + bk + lx];
    __syncthreads();
#pragma unroll
    for (int i = 0; i < 4; i++)
        g_wt[bk + ly + 8 * i][bo + lx] = t[lx][ly + 8 * i];
}

// ---------------------------------------------------------------------------
// SGEMM: C[m,o] = sum_k A[m,k]*W[o,k], k strictly sequential fp32 per output
// (must reproduce reference rounding; tensor-core adder trees flip spikes).
// 128x128x16 tile, 256 threads, 8x8/thread, double-buffered smem.
// W tiles via cp.async from pre-transposed g_wt; A register-prefetched.
// Inner product via packed fma.rn.f32x2. BN partials fused in epilogue.
// (Best-measured GEMM variant — R7.)
// ---------------------------------------------------------------------------
#define BM 128
#define BNb 128
#define BK 16
#define SPAD 4
#define WROW (BNb + SPAD)

__global__ void __launch_bounds__(256, 2)
gemm_k(const float* __restrict__ A) {
    __shared__ float As[2][BK][BM + SPAD];
    __shared__ float Ws[2][BK][WROW];

    const int tid = threadIdx.x;
    const int tx = tid & 15;
    const int ty = tid >> 4;
    const int m0 = blockIdx.y * BM;
    const int n0 = blockIdx.x * BNb;

    const int ar0 = ty * 4;
    const int bc0 = tx * 4;

    // A global-load mapping: 2 float4 per thread per stage
    const int lrow0 = tid >> 2;          // 0..63
    const int lkv   = (tid & 3) * 4;     // 0,4,8,12
    const float* Aptr0 = A + (size_t)(m0 + lrow0) * CIN + lkv;
    const size_t row64 = (size_t)64 * CIN;

    // W cp.async mapping: 2 chunks of 16B per thread per stage
    const int wk0 = tid >> 5;            // 0..7
    const int wc0 = tid & 31;
    const int wk1 = wk0 + 8;             // 8..15
    const uint32_t ws_u = smem_u32(&Ws[0][0][0]);
    const float* wsrc0 = &g_wt[wk0][n0 + wc0 * 4];
    const float* wsrc1 = &g_wt[wk1][n0 + wc0 * 4];

    auto load_W = [&](int buf, int k0) {
        const uint32_t base = ws_u + (uint32_t)buf * (BK * WROW * 4);
        cp_async16(base + (wk0 * WROW + wc0 * 4) * 4, wsrc0 + (size_t)k0 * COUT);
        cp_async16(base + (wk1 * WROW + wc0 * 4) * 4, wsrc1 + (size_t)k0 * COUT);
        asm volatile("cp.async.commit_group;" ::: "memory");
    };

    unsigned long long acc[8][4];
#pragma unroll
    for (int i = 0; i < 8; i++)
#pragma unroll
        for (int j = 0; j < 4; j++) acc[i][j] = 0ULL;

    // ---- prologue: stage 0
    {
        load_W(0, 0);
        float4 ra0 = *reinterpret_cast<const float4*>(Aptr0);
        float4 ra1 = *reinterpret_cast<const float4*>(Aptr0 + row64);
        As[0][lkv + 0][lrow0] = ra0.x; As[0][lkv + 1][lrow0] = ra0.y;
        As[0][lkv + 2][lrow0] = ra0.z; As[0][lkv + 3][lrow0] = ra0.w;
        As[0][lkv + 0][lrow0 + 64] = ra1.x; As[0][lkv + 1][lrow0 + 64] = ra1.y;
        As[0][lkv + 2][lrow0 + 64] = ra1.z; As[0][lkv + 3][lrow0 + 64] = ra1.w;
    }
    asm volatile("cp.async.wait_group 0;" ::: "memory");
    __syncthreads();

    const int NSTAGE = CIN / BK;   // 32
    float4 ra0, ra1;

#pragma unroll 1
    for (int s = 0; s < NSTAGE; s++) {
        const int cur = s & 1;
        const int nxt = cur ^ 1;

        if (s + 1 < NSTAGE) {
            const int koff = (s + 1) * BK;
            load_W(nxt, koff);
            ra0 = *reinterpret_cast<const float4*>(Aptr0 + koff);
            ra1 = *reinterpret_cast<const float4*>(Aptr0 + row64 + koff);
        }

#pragma unroll
        for (int kk = 0; kk < BK; kk++) {
            float4 a0 = *reinterpret_cast<const float4*>(&As[cur][kk][ar0]);
            float4 a1 = *reinterpret_cast<const float4*>(&As[cur][kk][ar0 + 64]);
            float4 b0 = *reinterpret_cast<const float4*>(&Ws[cur][kk][bc0]);
            float4 b1 = *reinterpret_cast<const float4*>(&Ws[cur][kk][bc0 + 64]);
            unsigned long long bp[4];
            bp[0] = *reinterpret_cast<unsigned long long*>(&b0.x);
            bp[1] = *reinterpret_cast<unsigned long long*>(&b0.z);
            bp[2] = *reinterpret_cast<unsigned long long*>(&b1.x);
            bp[3] = *reinterpret_cast<unsigned long long*>(&b1.z);

            const float a[8] = {a0.x, a0.y, a0.z, a0.w, a1.x, a1.y, a1.z, a1.w};
#pragma unroll
            for (int i = 0; i < 8; i++) {
                const unsigned long long ap = pack_dup(a[i]);
#pragma unroll
                for (int jp = 0; jp < 4; jp++)
                    fma2(acc[i][jp], ap, bp[jp]);
            }
        }

        if (s + 1 < NSTAGE) {
            As[nxt][lkv + 0][lrow0] = ra0.x; As[nxt][lkv + 1][lrow0] = ra0.y;
            As[nxt][lkv + 2][lrow0] = ra0.z; As[nxt][lkv + 3][lrow0] = ra0.w;
            As[nxt][lkv + 0][lrow0 + 64] = ra1.x; As[nxt][lkv + 1][lrow0 + 64] = ra1.y;
            As[nxt][lkv + 2][lrow0 + 64] = ra1.z; As[nxt][lkv + 3][lrow0 + 64] = ra1.w;
            asm volatile("cp.async.wait_group 0;" ::: "memory");
            __syncthreads();
        }
    }

    float acc_f[8][8];
#pragma unroll
    for (int i = 0; i < 8; i++)
#pragma unroll
        for (int jp = 0; jp < 4; jp++) {
            float2 v = unpack2(acc[i][jp]);
            acc_f[i][2 * jp + 0] = v.x;
            acc_f[i][2 * jp + 1] = v.y;
        }

    // ---- store C tile
#pragma unroll
    for (int ih = 0; ih < 2; ih++) {
#pragma unroll
        for (int i = 0; i < 4; i++) {
            const size_t m = (size_t)(m0 + ih * 64 + ar0 + i);
            const int ia = ih * 4 + i;
            float4 v0 = make_float4(acc_f[ia][0], acc_f[ia][1], acc_f[ia][2], acc_f[ia][3]);
            float4 v1 = make_float4(acc_f[ia][4], acc_f[ia][5], acc_f[ia][6], acc_f[ia][7]);
            *reinterpret_cast<float4*>(&g_y[m * COUT + n0 + bc0])      = v0;
            *reinterpret_cast<float4*>(&g_y[m * COUT + n0 + 64 + bc0]) = v1;
        }
    }

    // ---- fused BN partial stats (deterministic tree; reuse smem)
    __syncthreads();
    float* sred = &As[0][0][0];   // [16][128]
    float* qred = &As[1][0][0];   // [16][128]

    float s8[8], q8[8];
#pragma unroll
    for (int j = 0; j < 8; j++) { s8[j] = 0.0f; q8[j] = 0.0f; }
#pragma unroll
    for (int i = 0; i < 8; i++)
#pragma unroll
        for (int j = 0; j < 8; j++) {
            float v = acc_f[i][j];
            s8[j] += v;
            q8[j] = fmaf(v, v, q8[j]);
        }
#pragma unroll
    for (int jh = 0; jh < 2; jh++)
#pragma unroll
        for (int j = 0; j < 4; j++) {
            int c = jh * 64 + bc0 + j;
            sred[ty * 128 + c] = s8[jh * 4 + j];
            qred[ty * 128 + c] = q8[jh * 4 + j];
        }
    __syncthreads();

    if (tid < 128) {
        float s = 0.0f, q = 0.0f;
#pragma unroll
        for (int k = 0; k < 16; k++) {
            s += sred[k * 128 + tid];
            q += qred[k * 128 + tid];
        }
        g_psum[(size_t)blockIdx.y * COUT + n0 + tid] = s;
        g_psq [(size_t)blockIdx.y * COUT + n0 + tid] = q;
    }
}

// ---------------------------------------------------------------------------
// Finalize mean / rstd per channel. Same per-channel SEQUENTIAL loop as
// before (bitwise-identical result) but spread across 32 blocks so it isn't
// serialized on one SM (was ~30us; now ~3us).
// ---------------------------------------------------------------------------
__global__ void __launch_bounds__(16)
stats2_k() {
    const int o = blockIdx.x * 16 + threadIdx.x;   // 32 blocks x 16 ch
    float s = 0.0f, sq = 0.0f;
#pragma unroll 4
    for (int i = 0; i < NPART; i++) {
        s  += g_psum[i * COUT + o];
        sq += g_psq [i * COUT + o];
    }
    const float inv_m = 1.0f / (float)M_TOTAL;
    float mean = s * inv_m;
    float var  = sq * inv_m - mean * mean;
    g_mean[o] = mean;
    g_rstd[o] = rsqrtf(var + 1e-5f);
}

// ---------------------------------------------------------------------------
// Fused BN + multistep LIF + output store, float4-vectorized over channels.
// Per-lane math identical to scalar version -> bitwise-identical spikes.
// ---------------------------------------------------------------------------
__global__ void __launch_bounds__(256)
lif_k(const float* __restrict__ gamma, const float* __restrict__ beta,
      float* __restrict__ out) {
    const int idx = blockIdx.x * blockDim.x + threadIdx.x;   // vec4 index
    const int total4 = B_BATCH * N_SEQ * COUT / 4;
    if (idx >= total4) return;
    const int o4 = (idx & (COUT / 4 - 1)) * 4;               // channel base

    const float4 mean = *reinterpret_cast<const float4*>(&g_mean[o4]);
    const float4 rstd = *reinterpret_cast<const float4*>(&g_rstd[o4]);
    const float4 ga   = *reinterpret_cast<const float4*>(&gamma[o4]);
    const float4 be   = *reinterpret_cast<const float4*>(&beta[o4]);

    const size_t stride4 = (size_t)B_BATCH * N_SEQ * COUT / 4;
    const size_t base = (size_t)idx;
    const float4* yv = reinterpret_cast<const float4*>(g_y);
    float4* ov = reinterpret_cast<float4*>(out);

    float v0 = 0.0f, v1 = 0.0f, v2 = 0.0f, v3 = 0.0f;
#pragma unroll
    for (int t = 0; t < T_STEPS; t++) {
        const size_t off = base + (size_t)t * stride4;
        float4 raw = yv[off];
        float4 sp;
        {   // lane 0
            float xt = (raw.x - mean.x) * rstd.x; xt = xt * ga.x + be.x;
            v0 = v0 + (xt - v0) * 0.5f;
            sp.x = (v0 >= 1.0f) ? 1.0f : 0.0f;
            v0 = v0 * (1.0f - sp.x);
        }
        {   // lane 1
            float xt = (raw.y - mean.y) * rstd.y; xt = xt * ga.y + be.y;
            v1 = v1 + (xt - v1) * 0.5f;
            sp.y = (v1 >= 1.0f) ? 1.0f : 0.0f;
            v1 = v1 * (1.0f - sp.y);
        }
        {   // lane 2
            float xt = (raw.z - mean.z) * rstd.z; xt = xt * ga.z + be.z;
            v2 = v2 + (xt - v2) * 0.5f;
            sp.z = (v2 >= 1.0f) ? 1.0f : 0.0f;
            v2 = v2 * (1.0f - sp.z);
        }
        {   // lane 3
            float xt = (raw.w - mean.w) * rstd.w; xt = xt * ga.w + be.w;
            v3 = v3 + (xt - v3) * 0.5f;
            sp.w = (v3 >= 1.0f) ? 1.0f : 0.0f;
            v3 = v3 * (1.0f - sp.w);
        }
        ov[off] = sp;
    }
}

// ---------------------------------------------------------------------------
extern "C" void kernel_launch(void* const* d_in, const int* in_sizes, int n_in,
                              void* d_out, int out_size) {
    const float* x     = (const float*)d_in[0];
    const float* W     = (const float*)d_in[1];
    const float* gamma = (const float*)d_in[2];
    const float* beta  = (const float*)d_in[3];
    float* out = (float*)d_out;

    dim3 wt_grid(COUT / 32, CIN / 32);
    wt_k<<<wt_grid, 256>>>(W);

    dim3 gemm_grid(COUT / BNb, M_TOTAL / BM);    // (4, 1024)
    gemm_k<<<gemm_grid, 256>>>(x);

    stats2_k<<<32, 16>>>();

    const int total4 = B_BATCH * N_SEQ * COUT / 4;   // 4.19M vec4
    lif_k<<<(total4 + 255) / 256, 256>>>(gamma, beta, out);
}

// round 10
// speedup vs baseline: 1.1160x; 1.1160x over previous
#include <cuda_runtime.h>
#include <cstdint>

// Problem constants (fixed shapes from reference setup_inputs)
#define T_STEPS 4
#define B_BATCH 32            // TB / T = 128/4
#define N_SEQ   1024
#define CIN     512
#define COUT    512
#define M_TOTAL (T_STEPS * B_BATCH * N_SEQ)   // 131072 rows

// Scratch in device globals (no allocations allowed)
__device__ float g_y[(size_t)M_TOTAL * COUT];      // 268 MB GEMM output
__device__ float g_wt[CIN][COUT];                   // W transposed: [k][o], 1 MB
#define NPART 1024
__device__ float g_psum[NPART * COUT];
__device__ float g_psq [NPART * COUT];
__device__ float g_psum2[32 * COUT];
__device__ float g_psq2 [32 * COUT];
__device__ float g_mean[COUT];
__device__ float g_rstd[COUT];

// ---------------------------------------------------------------------------
// Packed f32x2 helpers (per-lane bitwise-identical to scalar fmaf).
// ---------------------------------------------------------------------------
__device__ __forceinline__ unsigned long long pack_dup(float a) {
    unsigned long long u;
    asm("mov.b64 %0, {%1, %1};" : "=l"(u) : "f"(a));
    return u;
}
__device__ __forceinline__ void fma2(unsigned long long& acc,
                                     unsigned long long a,
                                     unsigned long long b) {
    asm("fma.rn.f32x2 %0, %1, %2, %0;" : "+l"(acc) : "l"(a), "l"(b));
}
__device__ __forceinline__ float2 unpack2(unsigned long long u) {
    float lo, hi;
    asm("mov.b64 {%0, %1}, %2;" : "=f"(lo), "=f"(hi) : "l"(u));
    return make_float2(lo, hi);
}
__device__ __forceinline__ uint32_t smem_u32(const void* p) {
    uint32_t a;
    asm("{ .reg .u64 t; cvta.to.shared.u64 t, %1; cvt.u32.u64 %0, t; }" : "=r"(a) : "l"(p));
    return a;
}
__device__ __forceinline__ void cp_async16(uint32_t dst, const void* src) {
    asm volatile("cp.async.cg.shared.global [%0], [%1], 16;" :: "r"(dst), "l"(src) : "memory");
}

// ---------------------------------------------------------------------------
// Tiled transpose: g_wt[k][o] = W[o][k].
// ---------------------------------------------------------------------------
__global__ void __launch_bounds__(256)
wt_k(const float* __restrict__ W) {
    __shared__ float t[32][33];
    const int bo = blockIdx.x * 32;
    const int bk = blockIdx.y * 32;
    const int lx = threadIdx.x & 31;
    const int ly = threadIdx.x >> 5;
#pragma unroll
    for (int i = 0; i < 4; i++)
        t[ly + 8 * i][lx] = W[(size_t)(bo + ly + 8 * i) * CIN + bk + lx];
    __syncthreads();
#pragma unroll
    for (int i = 0; i < 4; i++)
        g_wt[bk + ly + 8 * i][bo + lx] = t[lx][ly + 8 * i];
}

// ---------------------------------------------------------------------------
// SGEMM: C[m,o] = sum_k A[m,k]*W[o,k], k strictly sequential fp32 per output
// (must reproduce reference rounding; tensor-core adder trees flip spikes).
// 128x128x16 tile, 256 threads, 8x8/thread, double-buffered smem.
// W tiles via cp.async from pre-transposed g_wt; A register-prefetched.
// Inner product via packed fma.rn.f32x2. BN partials fused in epilogue.
// (Best-measured GEMM variant — R7, unchanged.)
// ---------------------------------------------------------------------------
#define BM 128
#define BNb 128
#define BK 16
#define SPAD 4
#define WROW (BNb + SPAD)

__global__ void __launch_bounds__(256, 2)
gemm_k(const float* __restrict__ A) {
    __shared__ float As[2][BK][BM + SPAD];
    __shared__ float Ws[2][BK][WROW];

    const int tid = threadIdx.x;
    const int tx = tid & 15;
    const int ty = tid >> 4;
    const int m0 = blockIdx.y * BM;
    const int n0 = blockIdx.x * BNb;

    const int ar0 = ty * 4;
    const int bc0 = tx * 4;

    const int lrow0 = tid >> 2;          // 0..63
    const int lkv   = (tid & 3) * 4;     // 0,4,8,12
    const float* Aptr0 = A + (size_t)(m0 + lrow0) * CIN + lkv;
    const size_t row64 = (size_t)64 * CIN;

    const int wk0 = tid >> 5;            // 0..7
    const int wc0 = tid & 31;
    const int wk1 = wk0 + 8;             // 8..15
    const uint32_t ws_u = smem_u32(&Ws[0][0][0]);
    const float* wsrc0 = &g_wt[wk0][n0 + wc0 * 4];
    const float* wsrc1 = &g_wt[wk1][n0 + wc0 * 4];

    auto load_W = [&](int buf, int k0) {
        const uint32_t base = ws_u + (uint32_t)buf * (BK * WROW * 4);
        cp_async16(base + (wk0 * WROW + wc0 * 4) * 4, wsrc0 + (size_t)k0 * COUT);
        cp_async16(base + (wk1 * WROW + wc0 * 4) * 4, wsrc1 + (size_t)k0 * COUT);
        asm volatile("cp.async.commit_group;" ::: "memory");
    };

    unsigned long long acc[8][4];
#pragma unroll
    for (int i = 0; i < 8; i++)
#pragma unroll
        for (int j = 0; j < 4; j++) acc[i][j] = 0ULL;

    // ---- prologue: stage 0
    {
        load_W(0, 0);
        float4 ra0 = *reinterpret_cast<const float4*>(Aptr0);
        float4 ra1 = *reinterpret_cast<const float4*>(Aptr0 + row64);
        As[0][lkv + 0][lrow0] = ra0.x; As[0][lkv + 1][lrow0] = ra0.y;
        As[0][lkv + 2][lrow0] = ra0.z; As[0][lkv + 3][lrow0] = ra0.w;
        As[0][lkv + 0][lrow0 + 64] = ra1.x; As[0][lkv + 1][lrow0 + 64] = ra1.y;
        As[0][lkv + 2][lrow0 + 64] = ra1.z; As[0][lkv + 3][lrow0 + 64] = ra1.w;
    }
    asm volatile("cp.async.wait_group 0;" ::: "memory");
    __syncthreads();

    const int NSTAGE = CIN / BK;   // 32
    float4 ra0, ra1;

#pragma unroll 1
    for (int s = 0; s < NSTAGE; s++) {
        const int cur = s & 1;
        const int nxt = cur ^ 1;

        if (s + 1 < NSTAGE) {
            const int koff = (s + 1) * BK;
            load_W(nxt, koff);
            ra0 = *reinterpret_cast<const float4*>(Aptr0 + koff);
            ra1 = *reinterpret_cast<const float4*>(Aptr0 + row64 + koff);
        }

#pragma unroll
        for (int kk = 0; kk < BK; kk++) {
            float4 a0 = *reinterpret_cast<const float4*>(&As[cur][kk][ar0]);
            float4 a1 = *reinterpret_cast<const float4*>(&As[cur][kk][ar0 + 64]);
            float4 b0 = *reinterpret_cast<const float4*>(&Ws[cur][kk][bc0]);
            float4 b1 = *reinterpret_cast<const float4*>(&Ws[cur][kk][bc0 + 64]);
            unsigned long long bp[4];
            bp[0] = *reinterpret_cast<unsigned long long*>(&b0.x);
            bp[1] = *reinterpret_cast<unsigned long long*>(&b0.z);
            bp[2] = *reinterpret_cast<unsigned long long*>(&b1.x);
            bp[3] = *reinterpret_cast<unsigned long long*>(&b1.z);

            const float a[8] = {a0.x, a0.y, a0.z, a0.w, a1.x, a1.y, a1.z, a1.w};
#pragma unroll
            for (int i = 0; i < 8; i++) {
                const unsigned long long ap = pack_dup(a[i]);
#pragma unroll
                for (int jp = 0; jp < 4; jp++)
                    fma2(acc[i][jp], ap, bp[jp]);
            }
        }

        if (s + 1 < NSTAGE) {
            As[nxt][lkv + 0][lrow0] = ra0.x; As[nxt][lkv + 1][lrow0] = ra0.y;
            As[nxt][lkv + 2][lrow0] = ra0.z; As[nxt][lkv + 3][lrow0] = ra0.w;
            As[nxt][lkv + 0][lrow0 + 64] = ra1.x; As[nxt][lkv + 1][lrow0 + 64] = ra1.y;
            As[nxt][lkv + 2][lrow0 + 64] = ra1.z; As[nxt][lkv + 3][lrow0 + 64] = ra1.w;
            asm volatile("cp.async.wait_group 0;" ::: "memory");
            __syncthreads();
        }
    }

    float acc_f[8][8];
#pragma unroll
    for (int i = 0; i < 8; i++)
#pragma unroll
        for (int jp = 0; jp < 4; jp++) {
            float2 v = unpack2(acc[i][jp]);
            acc_f[i][2 * jp + 0] = v.x;
            acc_f[i][2 * jp + 1] = v.y;
        }

    // ---- store C tile
#pragma unroll
    for (int ih = 0; ih < 2; ih++) {
#pragma unroll
        for (int i = 0; i < 4; i++) {
            const size_t m = (size_t)(m0 + ih * 64 + ar0 + i);
            const int ia = ih * 4 + i;
            float4 v0 = make_float4(acc_f[ia][0], acc_f[ia][1], acc_f[ia][2], acc_f[ia][3]);
            float4 v1 = make_float4(acc_f[ia][4], acc_f[ia][5], acc_f[ia][6], acc_f[ia][7]);
            *reinterpret_cast<float4*>(&g_y[m * COUT + n0 + bc0])      = v0;
            *reinterpret_cast<float4*>(&g_y[m * COUT + n0 + 64 + bc0]) = v1;
        }
    }

    // ---- fused BN partial stats (deterministic tree; reuse smem)
    __syncthreads();
    float* sred = &As[0][0][0];   // [16][128]
    float* qred = &As[1][0][0];   // [16][128]

    float s8[8], q8[8];
#pragma unroll
    for (int j = 0; j < 8; j++) { s8[j] = 0.0f; q8[j] = 0.0f; }
#pragma unroll
    for (int i = 0; i < 8; i++)
#pragma unroll
        for (int j = 0; j < 8; j++) {
            float v = acc_f[i][j];
            s8[j] += v;
            q8[j] = fmaf(v, v, q8[j]);
        }
#pragma unroll
    for (int jh = 0; jh < 2; jh++)
#pragma unroll
        for (int j = 0; j < 4; j++) {
            int c = jh * 64 + bc0 + j;
            sred[ty * 128 + c] = s8[jh * 4 + j];
            qred[ty * 128 + c] = q8[jh * 4 + j];
        }
    __syncthreads();

    if (tid < 128) {
        float s = 0.0f, q = 0.0f;
#pragma unroll
        for (int k = 0; k < 16; k++) {
            s += sred[k * 128 + tid];
            q += qred[k * 128 + tid];
        }
        g_psum[(size_t)blockIdx.y * COUT + n0 + tid] = s;
        g_psq [(size_t)blockIdx.y * COUT + n0 + tid] = q;
    }
}

// ---------------------------------------------------------------------------
// BN stats stage A: 32 blocks x 512 threads; block b sums partial rows
// b*32..b*32+31 for all channels (thread = channel -> fully coalesced,
// 16 warps of MLP per block).
// ---------------------------------------------------------------------------
__global__ void __launch_bounds__(COUT)
stats2a_k() {
    const int o = threadIdx.x;
    const int b = blockIdx.x;
    float s = 0.0f, sq = 0.0f;
#pragma unroll
    for (int i = 0; i < 32; i++) {
        s  += g_psum[(b * 32 + i) * COUT + o];
        sq += g_psq [(b * 32 + i) * COUT + o];
    }
    g_psum2[b * COUT + o] = s;
    g_psq2 [b * COUT + o] = sq;
}

// Stage B: finalize mean / rstd per channel (1 block, 512 threads, 32 adds).
__global__ void __launch_bounds__(COUT)
stats2b_k() {
    const int o = threadIdx.x;
    float s = 0.0f, sq = 0.0f;
#pragma unroll
    for (int i = 0; i < 32; i++) {
        s  += g_psum2[i * COUT + o];
        sq += g_psq2 [i * COUT + o];
    }
    const float inv_m = 1.0f / (float)M_TOTAL;
    float mean = s * inv_m;
    float var  = sq * inv_m - mean * mean;
    g_mean[o] = mean;
    g_rstd[o] = rsqrtf(var + 1e-5f);
}

// ---------------------------------------------------------------------------
// Fused BN + multistep LIF + output store, float4-vectorized over channels.
// Per-lane math identical to scalar version -> bitwise-identical spikes.
// ---------------------------------------------------------------------------
__global__ void __launch_bounds__(256)
lif_k(const float* __restrict__ gamma, const float* __restrict__ beta,
      float* __restrict__ out) {
    const int idx = blockIdx.x * blockDim.x + threadIdx.x;   // vec4 index
    const int total4 = B_BATCH * N_SEQ * COUT / 4;
    if (idx >= total4) return;
    const int o4 = (idx & (COUT / 4 - 1)) * 4;               // channel base

    const float4 mean = *reinterpret_cast<const float4*>(&g_mean[o4]);
    const float4 rstd = *reinterpret_cast<const float4*>(&g_rstd[o4]);
    const float4 ga   = *reinterpret_cast<const float4*>(&gamma[o4]);
    const float4 be   = *reinterpret_cast<const float4*>(&beta[o4]);

    const size_t stride4 = (size_t)B_BATCH * N_SEQ * COUT / 4;
    const size_t base = (size_t)idx;
    const float4* yv = reinterpret_cast<const float4*>(g_y);
    float4* ov = reinterpret_cast<float4*>(out);

    float v0 = 0.0f, v1 = 0.0f, v2 = 0.0f, v3 = 0.0f;
#pragma unroll
    for (int t = 0; t < T_STEPS; t++) {
        const size_t off = base + (size_t)t * stride4;
        float4 raw = yv[off];
        float4 sp;
        {   float xt = (raw.x - mean.x) * rstd.x; xt = xt * ga.x + be.x;
            v0 = v0 + (xt - v0) * 0.5f;
            sp.x = (v0 >= 1.0f) ? 1.0f : 0.0f;
            v0 = v0 * (1.0f - sp.x); }
        {   float xt = (raw.y - mean.y) * rstd.y; xt = xt * ga.y + be.y;
            v1 = v1 + (xt - v1) * 0.5f;
            sp.y = (v1 >= 1.0f) ? 1.0f : 0.0f;
            v1 = v1 * (1.0f - sp.y); }
        {   float xt = (raw.z - mean.z) * rstd.z; xt = xt * ga.z + be.z;
            v2 = v2 + (xt - v2) * 0.5f;
            sp.z = (v2 >= 1.0f) ? 1.0f : 0.0f;
            v2 = v2 * (1.0f - sp.z); }
        {   float xt = (raw.w - mean.w) * rstd.w; xt = xt * ga.w + be.w;
            v3 = v3 + (xt - v3) * 0.5f;
            sp.w = (v3 >= 1.0f) ? 1.0f : 0.0f;
            v3 = v3 * (1.0f - sp.w); }
        ov[off] = sp;
    }
}

// ---------------------------------------------------------------------------
extern "C" void kernel_launch(void* const* d_in, const int* in_sizes, int n_in,
                              void* d_out, int out_size) {
    const float* x     = (const float*)d_in[0];
    const float* W     = (const float*)d_in[1];
    const float* gamma = (const float*)d_in[2];
    const float* beta  = (const float*)d_in[3];
    float* out = (float*)d_out;

    dim3 wt_grid(COUT / 32, CIN / 32);
    wt_k<<<wt_grid, 256>>>(W);

    dim3 gemm_grid(COUT / BNb, M_TOTAL / BM);    // (4, 1024)
    gemm_k<<<gemm_grid, 256>>>(x);

    stats2a_k<<<32, COUT>>>();
    stats2b_k<<<1, COUT>>>();

    const int total4 = B_BATCH * N_SEQ * COUT / 4;   // 4.19M vec4
    lif_k<<<(total4 + 255) / 256, 256>>>(gamma, beta, out);
}

// round 11
// speedup vs baseline: 1.1165x; 1.0004x over previous
#include <cuda_runtime.h>
#include <cstdint>

// Problem constants (fixed shapes from reference setup_inputs)
#define T_STEPS 4
#define B_BATCH 32            // TB / T = 128/4
#define N_SEQ   1024
#define CIN     512
#define COUT    512
#define M_TOTAL (T_STEPS * B_BATCH * N_SEQ)   // 131072 rows

// Scratch in device globals (no allocations allowed)
__device__ float g_y[(size_t)M_TOTAL * COUT];      // 268 MB GEMM output
__device__ float g_wt[CIN][COUT];                   // W transposed: [k][o], 1 MB
#define NPART 1024
#define NP2   64
__device__ float g_psum[NPART * COUT];
__device__ float g_psq [NPART * COUT];
__device__ float g_psum2[NP2 * COUT];
__device__ float g_psq2 [NP2 * COUT];
__device__ float g_mean[COUT];
__device__ float g_rstd[COUT];

// ---------------------------------------------------------------------------
// Packed f32x2 helpers (per-lane bitwise-identical to scalar fmaf).
// ---------------------------------------------------------------------------
__device__ __forceinline__ unsigned long long pack_dup(float a) {
    unsigned long long u;
    asm("mov.b64 %0, {%1, %1};" : "=l"(u) : "f"(a));
    return u;
}
__device__ __forceinline__ void fma2(unsigned long long& acc,
                                     unsigned long long a,
                                     unsigned long long b) {
    asm("fma.rn.f32x2 %0, %1, %2, %0;" : "+l"(acc) : "l"(a), "l"(b));
}
__device__ __forceinline__ float2 unpack2(unsigned long long u) {
    float lo, hi;
    asm("mov.b64 {%0, %1}, %2;" : "=f"(lo), "=f"(hi) : "l"(u));
    return make_float2(lo, hi);
}
__device__ __forceinline__ uint32_t smem_u32(const void* p) {
    uint32_t a;
    asm("{ .reg .u64 t; cvta.to.shared.u64 t, %1; cvt.u32.u64 %0, t; }" : "=r"(a) : "l"(p));
    return a;
}
__device__ __forceinline__ void cp_async16(uint32_t dst, const void* src) {
    asm volatile("cp.async.cg.shared.global [%0], [%1], 16;" :: "r"(dst), "l"(src) : "memory");
}

// ---------------------------------------------------------------------------
// Tiled transpose: g_wt[k][o] = W[o][k].
// ---------------------------------------------------------------------------
__global__ void __launch_bounds__(256)
wt_k(const float* __restrict__ W) {
    __shared__ float t[32][33];
    const int bo = blockIdx.x * 32;
    const int bk = blockIdx.y * 32;
    const int lx = threadIdx.x & 31;
    const int ly = threadIdx.x >> 5;
#pragma unroll
    for (int i = 0; i < 4; i++)
        t[ly + 8 * i][lx] = W[(size_t)(bo + ly + 8 * i) * CIN + bk + lx];
    __syncthreads();
#pragma unroll
    for (int i = 0; i < 4; i++)
        g_wt[bk + ly + 8 * i][bo + lx] = t[lx][ly + 8 * i];
}

// ---------------------------------------------------------------------------
// SGEMM: C[m,o] = sum_k A[m,k]*W[o,k], k strictly sequential fp32 per output
// (must reproduce reference rounding; tensor-core adder trees flip spikes).
// 128x128x16 tile, 256 threads, 8x8/thread, double-buffered smem.
// W tiles via cp.async from pre-transposed g_wt; A register-prefetched.
// Inner product via packed fma.rn.f32x2. BN partials fused in epilogue.
// (Best-measured GEMM variant — R7, unchanged.)
// ---------------------------------------------------------------------------
#define BM 128
#define BNb 128
#define BK 16
#define SPAD 4
#define WROW (BNb + SPAD)

__global__ void __launch_bounds__(256, 2)
gemm_k(const float* __restrict__ A) {
    __shared__ float As[2][BK][BM + SPAD];
    __shared__ float Ws[2][BK][WROW];

    const int tid = threadIdx.x;
    const int tx = tid & 15;
    const int ty = tid >> 4;
    const int m0 = blockIdx.y * BM;
    const int n0 = blockIdx.x * BNb;

    const int ar0 = ty * 4;
    const int bc0 = tx * 4;

    const int lrow0 = tid >> 2;          // 0..63
    const int lkv   = (tid & 3) * 4;     // 0,4,8,12
    const float* Aptr0 = A + (size_t)(m0 + lrow0) * CIN + lkv;
    const size_t row64 = (size_t)64 * CIN;

    const int wk0 = tid >> 5;            // 0..7
    const int wc0 = tid & 31;
    const int wk1 = wk0 + 8;             // 8..15
    const uint32_t ws_u = smem_u32(&Ws[0][0][0]);
    const float* wsrc0 = &g_wt[wk0][n0 + wc0 * 4];
    const float* wsrc1 = &g_wt[wk1][n0 + wc0 * 4];

    auto load_W = [&](int buf, int k0) {
        const uint32_t base = ws_u + (uint32_t)buf * (BK * WROW * 4);
        cp_async16(base + (wk0 * WROW + wc0 * 4) * 4, wsrc0 + (size_t)k0 * COUT);
        cp_async16(base + (wk1 * WROW + wc0 * 4) * 4, wsrc1 + (size_t)k0 * COUT);
        asm volatile("cp.async.commit_group;" ::: "memory");
    };

    unsigned long long acc[8][4];
#pragma unroll
    for (int i = 0; i < 8; i++)
#pragma unroll
        for (int j = 0; j < 4; j++) acc[i][j] = 0ULL;

    // ---- prologue: stage 0
    {
        load_W(0, 0);
        float4 ra0 = *reinterpret_cast<const float4*>(Aptr0);
        float4 ra1 = *reinterpret_cast<const float4*>(Aptr0 + row64);
        As[0][lkv + 0][lrow0] = ra0.x; As[0][lkv + 1][lrow0] = ra0.y;
        As[0][lkv + 2][lrow0] = ra0.z; As[0][lkv + 3][lrow0] = ra0.w;
        As[0][lkv + 0][lrow0 + 64] = ra1.x; As[0][lkv + 1][lrow0 + 64] = ra1.y;
        As[0][lkv + 2][lrow0 + 64] = ra1.z; As[0][lkv + 3][lrow0 + 64] = ra1.w;
    }
    asm volatile("cp.async.wait_group 0;" ::: "memory");
    __syncthreads();

    const int NSTAGE = CIN / BK;   // 32
    float4 ra0, ra1;

#pragma unroll 1
    for (int s = 0; s < NSTAGE; s++) {
        const int cur = s & 1;
        const int nxt = cur ^ 1;

        if (s + 1 < NSTAGE) {
            const int koff = (s + 1) * BK;
            load_W(nxt, koff);
            ra0 = *reinterpret_cast<const float4*>(Aptr0 + koff);
            ra1 = *reinterpret_cast<const float4*>(Aptr0 + row64 + koff);
        }

#pragma unroll
        for (int kk = 0; kk < BK; kk++) {
            float4 a0 = *reinterpret_cast<const float4*>(&As[cur][kk][ar0]);
            float4 a1 = *reinterpret_cast<const float4*>(&As[cur][kk][ar0 + 64]);
            float4 b0 = *reinterpret_cast<const float4*>(&Ws[cur][kk][bc0]);
            float4 b1 = *reinterpret_cast<const float4*>(&Ws[cur][kk][bc0 + 64]);
            unsigned long long bp[4];
            bp[0] = *reinterpret_cast<unsigned long long*>(&b0.x);
            bp[1] = *reinterpret_cast<unsigned long long*>(&b0.z);
            bp[2] = *reinterpret_cast<unsigned long long*>(&b1.x);
            bp[3] = *reinterpret_cast<unsigned long long*>(&b1.z);

            const float a[8] = {a0.x, a0.y, a0.z, a0.w, a1.x, a1.y, a1.z, a1.w};
#pragma unroll
            for (int i = 0; i < 8; i++) {
                const unsigned long long ap = pack_dup(a[i]);
#pragma unroll
                for (int jp = 0; jp < 4; jp++)
                    fma2(acc[i][jp], ap, bp[jp]);
            }
        }

        if (s + 1 < NSTAGE) {
            As[nxt][lkv + 0][lrow0] = ra0.x; As[nxt][lkv + 1][lrow0] = ra0.y;
            As[nxt][lkv + 2][lrow0] = ra0.z; As[nxt][lkv + 3][lrow0] = ra0.w;
            As[nxt][lkv + 0][lrow0 + 64] = ra1.x; As[nxt][lkv + 1][lrow0 + 64] = ra1.y;
            As[nxt][lkv + 2][lrow0 + 64] = ra1.z; As[nxt][lkv + 3][lrow0 + 64] = ra1.w;
            asm volatile("cp.async.wait_group 0;" ::: "memory");
            __syncthreads();
        }
    }

    float acc_f[8][8];
#pragma unroll
    for (int i = 0; i < 8; i++)
#pragma unroll
        for (int jp = 0; jp < 4; jp++) {
            float2 v = unpack2(acc[i][jp]);
            acc_f[i][2 * jp + 0] = v.x;
            acc_f[i][2 * jp + 1] = v.y;
        }

    // ---- store C tile
#pragma unroll
    for (int ih = 0; ih < 2; ih++) {
#pragma unroll
        for (int i = 0; i < 4; i++) {
            const size_t m = (size_t)(m0 + ih * 64 + ar0 + i);
            const int ia = ih * 4 + i;
            float4 v0 = make_float4(acc_f[ia][0], acc_f[ia][1], acc_f[ia][2], acc_f[ia][3]);
            float4 v1 = make_float4(acc_f[ia][4], acc_f[ia][5], acc_f[ia][6], acc_f[ia][7]);
            *reinterpret_cast<float4*>(&g_y[m * COUT + n0 + bc0])      = v0;
            *reinterpret_cast<float4*>(&g_y[m * COUT + n0 + 64 + bc0]) = v1;
        }
    }

    // ---- fused BN partial stats (deterministic tree; reuse smem)
    __syncthreads();
    float* sred = &As[0][0][0];   // [16][128]
    float* qred = &As[1][0][0];   // [16][128]

    float s8[8], q8[8];
#pragma unroll
    for (int j = 0; j < 8; j++) { s8[j] = 0.0f; q8[j] = 0.0f; }
#pragma unroll
    for (int i = 0; i < 8; i++)
#pragma unroll
        for (int j = 0; j < 8; j++) {
            float v = acc_f[i][j];
            s8[j] += v;
            q8[j] = fmaf(v, v, q8[j]);
        }
#pragma unroll
    for (int jh = 0; jh < 2; jh++)
#pragma unroll
        for (int j = 0; j < 4; j++) {
            int c = jh * 64 + bc0 + j;
            sred[ty * 128 + c] = s8[jh * 4 + j];
            qred[ty * 128 + c] = q8[jh * 4 + j];
        }
    __syncthreads();

    if (tid < 128) {
        float s = 0.0f, q = 0.0f;
#pragma unroll
        for (int k = 0; k < 16; k++) {
            s += sred[k * 128 + tid];
            q += qred[k * 128 + tid];
        }
        g_psum[(size_t)blockIdx.y * COUT + n0 + tid] = s;
        g_psq [(size_t)blockIdx.y * COUT + n0 + tid] = q;
    }
}

// ---------------------------------------------------------------------------
// BN stats stage A: 64 blocks x 512 threads; block b sums partial rows
// b*16..b*16+15 for all channels (coalesced; thread = channel).
// ---------------------------------------------------------------------------
__global__ void __launch_bounds__(COUT)
stats2a_k() {
    const int o = threadIdx.x;
    const int b = blockIdx.x;
    float s = 0.0f, sq = 0.0f;
#pragma unroll
    for (int i = 0; i < NPART / NP2; i++) {
        s  += g_psum[(b * (NPART / NP2) + i) * COUT + o];
        sq += g_psq [(b * (NPART / NP2) + i) * COUT + o];
    }
    g_psum2[b * COUT + o] = s;
    g_psq2 [b * COUT + o] = sq;
}

// Stage B: finalize mean / rstd per channel (1 block, 512 threads).
__global__ void __launch_bounds__(COUT)
stats2b_k() {
    const int o = threadIdx.x;
    float s = 0.0f, sq = 0.0f;
#pragma unroll
    for (int i = 0; i < NP2; i++) {
        s  += g_psum2[i * COUT + o];
        sq += g_psq2 [i * COUT + o];
    }
    const float inv_m = 1.0f / (float)M_TOTAL;
    float mean = s * inv_m;
    float var  = sq * inv_m - mean * mean;
    g_mean[o] = mean;
    g_rstd[o] = rsqrtf(var + 1e-5f);
}

// ---------------------------------------------------------------------------
// Fused BN + multistep LIF + output store. Each thread handles TWO adjacent
// float4 groups (8 consecutive channels) -> 8 independent LDGs in flight,
// better MLP vs the 4-load version. Per-lane math identical to scalar
// version -> bitwise-identical spikes.
// ---------------------------------------------------------------------------
__device__ __forceinline__ void lif_lane(float raw, float mean, float rstd,
                                         float ga, float be, float& v, float& sp) {
    float xt = (raw - mean) * rstd;
    xt = xt * ga + be;
    v = v + (xt - v) * 0.5f;
    sp = (v >= 1.0f) ? 1.0f : 0.0f;
    v = v * (1.0f - sp);
}

__global__ void __launch_bounds__(256)
lif_k(const float* __restrict__ gamma, const float* __restrict__ beta,
      float* __restrict__ out) {
    const int idx8 = blockIdx.x * blockDim.x + threadIdx.x;   // vec8 index
    const int total8 = B_BATCH * N_SEQ * COUT / 8;
    if (idx8 >= total8) return;
    const int idx = idx8 * 2;                                  // first vec4
    const int o4 = (idx & (COUT / 4 - 1)) * 4;                 // channel base (o4, o4+4)

    const float4 meanA = *reinterpret_cast<const float4*>(&g_mean[o4]);
    const float4 meanB = *reinterpret_cast<const float4*>(&g_mean[o4 + 4]);
    const float4 rstdA = *reinterpret_cast<const float4*>(&g_rstd[o4]);
    const float4 rstdB = *reinterpret_cast<const float4*>(&g_rstd[o4 + 4]);
    const float4 gaA   = *reinterpret_cast<const float4*>(&gamma[o4]);
    const float4 gaB   = *reinterpret_cast<const float4*>(&gamma[o4 + 4]);
    const float4 beA   = *reinterpret_cast<const float4*>(&beta[o4]);
    const float4 beB   = *reinterpret_cast<const float4*>(&beta[o4 + 4]);

    const size_t stride4 = (size_t)B_BATCH * N_SEQ * COUT / 4;
    const float4* yv = reinterpret_cast<const float4*>(g_y);
    float4* ov = reinterpret_cast<float4*>(out);

    // hoist all 8 loads (independent addresses)
    float4 rA[T_STEPS], rB[T_STEPS];
#pragma unroll
    for (int t = 0; t < T_STEPS; t++) {
        const size_t off = (size_t)idx + (size_t)t * stride4;
        rA[t] = yv[off];
        rB[t] = yv[off + 1];
    }

    float vA0 = 0, vA1 = 0, vA2 = 0, vA3 = 0;
    float vB0 = 0, vB1 = 0, vB2 = 0, vB3 = 0;
#pragma unroll
    for (int t = 0; t < T_STEPS; t++) {
        const size_t off = (size_t)idx + (size_t)t * stride4;
        float4 spA, spB;
        lif_lane(rA[t].x, meanA.x, rstdA.x, gaA.x, beA.x, vA0, spA.x);
        lif_lane(rA[t].y, meanA.y, rstdA.y, gaA.y, beA.y, vA1, spA.y);
        lif_lane(rA[t].z, meanA.z, rstdA.z, gaA.z, beA.z, vA2, spA.z);
        lif_lane(rA[t].w, meanA.w, rstdA.w, gaA.w, beA.w, vA3, spA.w);
        lif_lane(rB[t].x, meanB.x, rstdB.x, gaB.x, beB.x, vB0, spB.x);
        lif_lane(rB[t].y, meanB.y, rstdB.y, gaB.y, beB.y, vB1, spB.y);
        lif_lane(rB[t].z, meanB.z, rstdB.z, gaB.z, beB.z, vB2, spB.z);
        lif_lane(rB[t].w, meanB.w, rstdB.w, gaB.w, beB.w, vB3, spB.w);
        ov[off]     = spA;
        ov[off + 1] = spB;
    }
}

// ---------------------------------------------------------------------------
extern "C" void kernel_launch(void* const* d_in, const int* in_sizes, int n_in,
                              void* d_out, int out_size) {
    const float* x     = (const float*)d_in[0];
    const float* W     = (const float*)d_in[1];
    const float* gamma = (const float*)d_in[2];
    const float* beta  = (const float*)d_in[3];
    float* out = (float*)d_out;

    dim3 wt_grid(COUT / 32, CIN / 32);
    wt_k<<<wt_grid, 256>>>(W);

    dim3 gemm_grid(COUT / BNb, M_TOTAL / BM);    // (4, 1024)
    gemm_k<<<gemm_grid, 256>>>(x);

    stats2a_k<<<NP2, COUT>>>();
    stats2b_k<<<1, COUT>>>();

    const int total8 = B_BATCH * N_SEQ * COUT / 8;   // 2.1M vec8
    lif_k<<<(total8 + 255) / 256, 256>>>(gamma, beta, out);
}

// round 12
// speedup vs baseline: 1.1390x; 1.0201x over previous
#include <cuda_runtime.h>
#include <cstdint>

// Problem constants (fixed shapes from reference setup_inputs)
#define T_STEPS 4
#define B_BATCH 32            // TB / T = 128/4
#define N_SEQ   1024
#define CIN     512
#define COUT    512
#define M_TOTAL (T_STEPS * B_BATCH * N_SEQ)   // 131072 rows

// Scratch in device globals (no allocations allowed)
__device__ float g_y[(size_t)M_TOTAL * COUT];      // 268 MB GEMM output
__device__ float g_wt[CIN][COUT];                   // W transposed: [k][o], 1 MB
#define NPART 1024
#define NP2   64
__device__ float g_psum[NPART * COUT];
__device__ float g_psq [NPART * COUT];
__device__ float g_psum2[NP2 * COUT];
__device__ float g_psq2 [NP2 * COUT];
__device__ float g_mean[COUT];
__device__ float g_rstd[COUT];

// ---------------------------------------------------------------------------
// Packed f32x2 helpers (per-lane bitwise-identical to scalar fmaf).
// ---------------------------------------------------------------------------
__device__ __forceinline__ unsigned long long pack_dup(float a) {
    unsigned long long u;
    asm("mov.b64 %0, {%1, %1};" : "=l"(u) : "f"(a));
    return u;
}
__device__ __forceinline__ void fma2(unsigned long long& acc,
                                     unsigned long long a,
                                     unsigned long long b) {
    asm("fma.rn.f32x2 %0, %1, %2, %0;" : "+l"(acc) : "l"(a), "l"(b));
}
__device__ __forceinline__ float2 unpack2(unsigned long long u) {
    float lo, hi;
    asm("mov.b64 {%0, %1}, %2;" : "=f"(lo), "=f"(hi) : "l"(u));
    return make_float2(lo, hi);
}
__device__ __forceinline__ uint32_t smem_u32(const void* p) {
    uint32_t a;
    asm("{ .reg .u64 t; cvta.to.shared.u64 t, %1; cvt.u32.u64 %0, t; }" : "=r"(a) : "l"(p));
    return a;
}
__device__ __forceinline__ void cp_async16(uint32_t dst, const void* src) {
    asm volatile("cp.async.cg.shared.global [%0], [%1], 16;" :: "r"(dst), "l"(src) : "memory");
}

// ---------------------------------------------------------------------------
// Tiled transpose: g_wt[k][o] = W[o][k].
// ---------------------------------------------------------------------------
__global__ void __launch_bounds__(256)
wt_k(const float* __restrict__ W) {
    __shared__ float t[32][33];
    const int bo = blockIdx.x * 32;
    const int bk = blockIdx.y * 32;
    const int lx = threadIdx.x & 31;
    const int ly = threadIdx.x >> 5;
#pragma unroll
    for (int i = 0; i < 4; i++)
        t[ly + 8 * i][lx] = W[(size_t)(bo + ly + 8 * i) * CIN + bk + lx];
    __syncthreads();
#pragma unroll
    for (int i = 0; i < 4; i++)
        g_wt[bk + ly + 8 * i][bo + lx] = t[lx][ly + 8 * i];
}

// ---------------------------------------------------------------------------
// SGEMM: C[m,o] = sum_k A[m,k]*W[o,k], k strictly sequential fp32 per output
// (must reproduce reference rounding; tensor-core adder trees flip spikes).
// 128x128x16 tile, 256 threads, 8x8/thread, double-buffered smem.
// Stage loop manually unrolled x2 -> all smem addresses are compile-time
// constants (no cur/nxt runtime indexing on the post-barrier critical path).
// W tiles via cp.async from pre-transposed g_wt; A register-prefetched.
// Inner product via packed fma.rn.f32x2 (bit-identical per lane).
// BN partials fused in epilogue (deterministic tree).
// ---------------------------------------------------------------------------
#define BM 128
#define BNb 128
#define BK 16
#define SPAD 4
#define WROW (BNb + SPAD)

__global__ void __launch_bounds__(256, 2)
gemm_k(const float* __restrict__ A) {
    __shared__ float As[2][BK][BM + SPAD];
    __shared__ float Ws[2][BK][WROW];

    const int tid = threadIdx.x;
    const int tx = tid & 15;
    const int ty = tid >> 4;
    const int m0 = blockIdx.y * BM;
    const int n0 = blockIdx.x * BNb;

    const int ar0 = ty * 4;
    const int bc0 = tx * 4;

    const int lrow0 = tid >> 2;          // 0..63
    const int lkv   = (tid & 3) * 4;     // 0,4,8,12
    const float* Aptr0 = A + (size_t)(m0 + lrow0) * CIN + lkv;
    const size_t row64 = (size_t)64 * CIN;

    const int wk0 = tid >> 5;            // 0..7
    const int wc0 = tid & 31;
    const int wk1 = wk0 + 8;             // 8..15
    const uint32_t ws_u = smem_u32(&Ws[0][0][0]);
    const float* wsrc0 = &g_wt[wk0][n0 + wc0 * 4];
    const float* wsrc1 = &g_wt[wk1][n0 + wc0 * 4];

    unsigned long long acc[8][4];
#pragma unroll
    for (int i = 0; i < 8; i++)
#pragma unroll
        for (int j = 0; j < 4; j++) acc[i][j] = 0ULL;

    // ---- building blocks (buf is a compile-time constant at each call) ----
    auto load_W = [&](int buf, int k0) {
        const uint32_t base = ws_u + (uint32_t)buf * (BK * WROW * 4);
        cp_async16(base + (wk0 * WROW + wc0 * 4) * 4, wsrc0 + (size_t)k0 * COUT);
        cp_async16(base + (wk1 * WROW + wc0 * 4) * 4, wsrc1 + (size_t)k0 * COUT);
        asm volatile("cp.async.commit_group;" ::: "memory");
    };
    auto store_A = [&](int buf, float4 ra0, float4 ra1) {
        As[buf][lkv + 0][lrow0] = ra0.x; As[buf][lkv + 1][lrow0] = ra0.y;
        As[buf][lkv + 2][lrow0] = ra0.z; As[buf][lkv + 3][lrow0] = ra0.w;
        As[buf][lkv + 0][lrow0 + 64] = ra1.x; As[buf][lkv + 1][lrow0 + 64] = ra1.y;
        As[buf][lkv + 2][lrow0 + 64] = ra1.z; As[buf][lkv + 3][lrow0 + 64] = ra1.w;
    };
    auto compute = [&](int buf) {
#pragma unroll
        for (int kk = 0; kk < BK; kk++) {
            float4 a0 = *reinterpret_cast<const float4*>(&As[buf][kk][ar0]);
            float4 a1 = *reinterpret_cast<const float4*>(&As[buf][kk][ar0 + 64]);
            float4 b0 = *reinterpret_cast<const float4*>(&Ws[buf][kk][bc0]);
            float4 b1 = *reinterpret_cast<const float4*>(&Ws[buf][kk][bc0 + 64]);
            unsigned long long bp[4];
            bp[0] = *reinterpret_cast<unsigned long long*>(&b0.x);
            bp[1] = *reinterpret_cast<unsigned long long*>(&b0.z);
            bp[2] = *reinterpret_cast<unsigned long long*>(&b1.x);
            bp[3] = *reinterpret_cast<unsigned long long*>(&b1.z);
            const float a[8] = {a0.x, a0.y, a0.z, a0.w, a1.x, a1.y, a1.z, a1.w};
#pragma unroll
            for (int i = 0; i < 8; i++) {
                const unsigned long long ap = pack_dup(a[i]);
#pragma unroll
                for (int jp = 0; jp < 4; jp++)
                    fma2(acc[i][jp], ap, bp[jp]);
            }
        }
    };

    // ---- prologue: stage 0 -> buffer 0
    {
        load_W(0, 0);
        float4 ra0 = *reinterpret_cast<const float4*>(Aptr0);
        float4 ra1 = *reinterpret_cast<const float4*>(Aptr0 + row64);
        store_A(0, ra0, ra1);
    }
    asm volatile("cp.async.wait_group 0;" ::: "memory");
    __syncthreads();

    // ---- main loop: 16 iterations x 2 stages, fixed buffer roles
    const int NPAIR = CIN / (2 * BK);    // 16
#pragma unroll 1
    for (int p = 0; p < NPAIR; p++) {
        const int k_even = 2 * p * BK;       // stage in buffer 0 (current)
        const int k_odd  = k_even + BK;      // next stage -> buffer 1

        // stage even (buf 0): prefetch odd into buf 1
        {
            load_W(1, k_odd);
            float4 ra0 = *reinterpret_cast<const float4*>(Aptr0 + k_odd);
            float4 ra1 = *reinterpret_cast<const float4*>(Aptr0 + row64 + k_odd);
            compute(0);
            store_A(1, ra0, ra1);
            asm volatile("cp.async.wait_group 0;" ::: "memory");
            __syncthreads();
        }

        // stage odd (buf 1): prefetch next even into buf 0 (unless last pair)
        if (p + 1 < NPAIR) {
            const int k_next = k_odd + BK;
            load_W(0, k_next);
            float4 ra0 = *reinterpret_cast<const float4*>(Aptr0 + k_next);
            float4 ra1 = *reinterpret_cast<const float4*>(Aptr0 + row64 + k_next);
            compute(1);
            store_A(0, ra0, ra1);
            asm volatile("cp.async.wait_group 0;" ::: "memory");
            __syncthreads();
        } else {
            compute(1);
        }
    }

    float acc_f[8][8];
#pragma unroll
    for (int i = 0; i < 8; i++)
#pragma unroll
        for (int jp = 0; jp < 4; jp++) {
            float2 v = unpack2(acc[i][jp]);
            acc_f[i][2 * jp + 0] = v.x;
            acc_f[i][2 * jp + 1] = v.y;
        }

    // ---- store C tile
#pragma unroll
    for (int ih = 0; ih < 2; ih++) {
#pragma unroll
        for (int i = 0; i < 4; i++) {
            const size_t m = (size_t)(m0 + ih * 64 + ar0 + i);
            const int ia = ih * 4 + i;
            float4 v0 = make_float4(acc_f[ia][0], acc_f[ia][1], acc_f[ia][2], acc_f[ia][3]);
            float4 v1 = make_float4(acc_f[ia][4], acc_f[ia][5], acc_f[ia][6], acc_f[ia][7]);
            *reinterpret_cast<float4*>(&g_y[m * COUT + n0 + bc0])      = v0;
            *reinterpret_cast<float4*>(&g_y[m * COUT + n0 + 64 + bc0]) = v1;
        }
    }

    // ---- fused BN partial stats (deterministic tree; reuse smem)
    __syncthreads();
    float* sred = &As[0][0][0];   // [16][128]
    float* qred = &As[1][0][0];   // [16][128]

    float s8[8], q8[8];
#pragma unroll
    for (int j = 0; j < 8; j++) { s8[j] = 0.0f; q8[j] = 0.0f; }
#pragma unroll
    for (int i = 0; i < 8; i++)
#pragma unroll
        for (int j = 0; j < 8; j++) {
            float v = acc_f[i][j];
            s8[j] += v;
            q8[j] = fmaf(v, v, q8[j]);
        }
#pragma unroll
    for (int jh = 0; jh < 2; jh++)
#pragma unroll
        for (int j = 0; j < 4; j++) {
            int c = jh * 64 + bc0 + j;
            sred[ty * 128 + c] = s8[jh * 4 + j];
            qred[ty * 128 + c] = q8[jh * 4 + j];
        }
    __syncthreads();

    if (tid < 128) {
        float s = 0.0f, q = 0.0f;
#pragma unroll
        for (int k = 0; k < 16; k++) {
            s += sred[k * 128 + tid];
            q += qred[k * 128 + tid];
        }
        g_psum[(size_t)blockIdx.y * COUT + n0 + tid] = s;
        g_psq [(size_t)blockIdx.y * COUT + n0 + tid] = q;
    }
}

// ---------------------------------------------------------------------------
// BN stats stage A: 64 blocks x 512 threads, coalesced.
// ---------------------------------------------------------------------------
__global__ void __launch_bounds__(COUT)
stats2a_k() {
    const int o = threadIdx.x;
    const int b = blockIdx.x;
    float s = 0.0f, sq = 0.0f;
#pragma unroll
    for (int i = 0; i < NPART / NP2; i++) {
        s  += g_psum[(b * (NPART / NP2) + i) * COUT + o];
        sq += g_psq [(b * (NPART / NP2) + i) * COUT + o];
    }
    g_psum2[b * COUT + o] = s;
    g_psq2 [b * COUT + o] = sq;
}

// Stage B: finalize mean / rstd. 256 threads, 2 channels each via float2
// (halves the dependent-load chain length per thread).
__global__ void __launch_bounds__(256)
stats2b_k() {
    const int o2 = threadIdx.x;            // pair index: channels 2*o2, 2*o2+1
    float2 s = make_float2(0.0f, 0.0f), sq = make_float2(0.0f, 0.0f);
#pragma unroll
    for (int i = 0; i < NP2; i++) {
        float2 a = *reinterpret_cast<const float2*>(&g_psum2[i * COUT + o2 * 2]);
        float2 b = *reinterpret_cast<const float2*>(&g_psq2 [i * COUT + o2 * 2]);
        s.x += a.x;  s.y += a.y;
        sq.x += b.x; sq.y += b.y;
    }
    const float inv_m = 1.0f / (float)M_TOTAL;
    float mean0 = s.x * inv_m, mean1 = s.y * inv_m;
    g_mean[o2 * 2 + 0] = mean0;
    g_mean[o2 * 2 + 1] = mean1;
    g_rstd[o2 * 2 + 0] = rsqrtf(sq.x * inv_m - mean0 * mean0 + 1e-5f);
    g_rstd[o2 * 2 + 1] = rsqrtf(sq.y * inv_m - mean1 * mean1 + 1e-5f);
}

// ---------------------------------------------------------------------------
// Fused BN + multistep LIF + output store (vec8 per thread; measured 74us).
// ---------------------------------------------------------------------------
__device__ __forceinline__ void lif_lane(float raw, float mean, float rstd,
                                         float ga, float be, float& v, float& sp) {
    float xt = (raw - mean) * rstd;
    xt = xt * ga + be;
    v = v + (xt - v) * 0.5f;
    sp = (v >= 1.0f) ? 1.0f : 0.0f;
    v = v * (1.0f - sp);
}

__global__ void __launch_bounds__(256)
lif_k(const float* __restrict__ gamma, const float* __restrict__ beta,
      float* __restrict__ out) {
    const int idx8 = blockIdx.x * blockDim.x + threadIdx.x;
    const int total8 = B_BATCH * N_SEQ * COUT / 8;
    if (idx8 >= total8) return;
    const int idx = idx8 * 2;
    const int o4 = (idx & (COUT / 4 - 1)) * 4;

    const float4 meanA = *reinterpret_cast<const float4*>(&g_mean[o4]);
    const float4 meanB = *reinterpret_cast<const float4*>(&g_mean[o4 + 4]);
    const float4 rstdA = *reinterpret_cast<const float4*>(&g_rstd[o4]);
    const float4 rstdB = *reinterpret_cast<const float4*>(&g_rstd[o4 + 4]);
    const float4 gaA   = *reinterpret_cast<const float4*>(&gamma[o4]);
    const float4 gaB   = *reinterpret_cast<const float4*>(&gamma[o4 + 4]);
    const float4 beA   = *reinterpret_cast<const float4*>(&beta[o4]);
    const float4 beB   = *reinterpret_cast<const float4*>(&beta[o4 + 4]);

    const size_t stride4 = (size_t)B_BATCH * N_SEQ * COUT / 4;
    const float4* yv = reinterpret_cast<const float4*>(g_y);
    float4* ov = reinterpret_cast<float4*>(out);

    float4 rA[T_STEPS], rB[T_STEPS];
#pragma unroll
    for (int t = 0; t < T_STEPS; t++) {
        const size_t off = (size_t)idx + (size_t)t * stride4;
        rA[t] = yv[off];
        rB[t] = yv[off + 1];
    }

    float vA0 = 0, vA1 = 0, vA2 = 0, vA3 = 0;
    float vB0 = 0, vB1 = 0, vB2 = 0, vB3 = 0;
#pragma unroll
    for (int t = 0; t < T_STEPS; t++) {
        const size_t off = (size_t)idx + (size_t)t * stride4;
        float4 spA, spB;
        lif_lane(rA[t].x, meanA.x, rstdA.x, gaA.x, beA.x, vA0, spA.x);
        lif_lane(rA[t].y, meanA.y, rstdA.y, gaA.y, beA.y, vA1, spA.y);
        lif_lane(rA[t].z, meanA.z, rstdA.z, gaA.z, beA.z, vA2, spA.z);
        lif_lane(rA[t].w, meanA.w, rstdA.w, gaA.w, beA.w, vA3, spA.w);
        lif_lane(rB[t].x, meanB.x, rstdB.x, gaB.x, beB.x, vB0, spB.x);
        lif_lane(rB[t].y, meanB.y, rstdB.y, gaB.y, beB.y, vB1, spB.y);
        lif_lane(rB[t].z, meanB.z, rstdB.z, gaB.z, beB.z, vB2, spB.z);
        lif_lane(rB[t].w, meanB.w, rstdB.w, gaB.w, beB.w, vB3, spB.w);
        ov[off]     = spA;
        ov[off + 1] = spB;
    }
}

// ---------------------------------------------------------------------------
extern "C" void kernel_launch(void* const* d_in, const int* in_sizes, int n_in,
                              void* d_out, int out_size) {
    const float* x     = (const float*)d_in[0];
    const float* W     = (const float*)d_in[1];
    const float* gamma = (const float*)d_in[2];
    const float* beta  = (const float*)d_in[3];
    float* out = (float*)d_out;

    dim3 wt_grid(COUT / 32, CIN / 32);
    wt_k<<<wt_grid, 256>>>(W);

    dim3 gemm_grid(COUT / BNb, M_TOTAL / BM);    // (4, 1024)
    gemm_k<<<gemm_grid, 256>>>(x);

    stats2a_k<<<NP2, COUT>>>();
    stats2b_k<<<1, 256>>>();

    const int total8 = B_BATCH * N_SEQ * COUT / 8;
    lif_k<<<(total8 + 255) / 256, 256>>>(gamma, beta, out);
}

// round 13
// speedup vs baseline: 1.1392x; 1.0001x over previous
#include <cuda_runtime.h>
#include <cstdint>

// Problem constants (fixed shapes from reference setup_inputs)
#define T_STEPS 4
#define B_BATCH 32            // TB / T = 128/4
#define N_SEQ   1024
#define CIN     512
#define COUT    512
#define M_TOTAL (T_STEPS * B_BATCH * N_SEQ)   // 131072 rows

// Scratch in device globals (no allocations allowed)
__device__ float g_y[(size_t)M_TOTAL * COUT];      // 268 MB GEMM output
__device__ float g_wt[CIN][COUT];                   // W transposed: [k][o], 1 MB
#define NPART 1024
#define NP2   64
__device__ float g_psum[NPART * COUT];
__device__ float g_psq [NPART * COUT];
__device__ float g_psum2[NP2 * COUT];
__device__ float g_psq2 [NP2 * COUT];
__device__ float g_mean[COUT];
__device__ float g_rstd[COUT];

// ---------------------------------------------------------------------------
// Packed f32x2 helpers (per-lane bitwise-identical to scalar fmaf).
// ---------------------------------------------------------------------------
__device__ __forceinline__ unsigned long long pack_dup(float a) {
    unsigned long long u;
    asm("mov.b64 %0, {%1, %1};" : "=l"(u) : "f"(a));
    return u;
}
__device__ __forceinline__ void fma2(unsigned long long& acc,
                                     unsigned long long a,
                                     unsigned long long b) {
    asm("fma.rn.f32x2 %0, %1, %2, %0;" : "+l"(acc) : "l"(a), "l"(b));
}
__device__ __forceinline__ float2 unpack2(unsigned long long u) {
    float lo, hi;
    asm("mov.b64 {%0, %1}, %2;" : "=f"(lo), "=f"(hi) : "l"(u));
    return make_float2(lo, hi);
}
__device__ __forceinline__ uint32_t smem_u32(const void* p) {
    uint32_t a;
    asm("{ .reg .u64 t; cvta.to.shared.u64 t, %1; cvt.u32.u64 %0, t; }" : "=r"(a) : "l"(p));
    return a;
}
__device__ __forceinline__ void cp_async16(uint32_t dst, const void* src) {
    asm volatile("cp.async.cg.shared.global [%0], [%1], 16;" :: "r"(dst), "l"(src) : "memory");
}

// ---------------------------------------------------------------------------
// Tiled transpose: g_wt[k][o] = W[o][k].
// ---------------------------------------------------------------------------
__global__ void __launch_bounds__(256)
wt_k(const float* __restrict__ W) {
    __shared__ float t[32][33];
    const int bo = blockIdx.x * 32;
    const int bk = blockIdx.y * 32;
    const int lx = threadIdx.x & 31;
    const int ly = threadIdx.x >> 5;
#pragma unroll
    for (int i = 0; i < 4; i++)
        t[ly + 8 * i][lx] = W[(size_t)(bo + ly + 8 * i) * CIN + bk + lx];
    __syncthreads();
#pragma unroll
    for (int i = 0; i < 4; i++)
        g_wt[bk + ly + 8 * i][bo + lx] = t[lx][ly + 8 * i];
}

// ---------------------------------------------------------------------------
// SGEMM: C[m,o] = sum_k A[m,k]*W[o,k], k strictly sequential fp32 per output
// (must reproduce reference rounding; tensor-core adder trees flip spikes).
// 128x128x16 tile, 256 threads, 8x8/thread, double-buffered smem.
// Stage loop manually unrolled x2 -> all smem addresses compile-time const.
// W tiles via cp.async from pre-transposed g_wt; A register-prefetched.
// Inner product via packed fma.rn.f32x2 (bit-identical per lane).
// BN partials fused in epilogue (deterministic tree).
// (Measured-best GEMM — R12, unchanged.)
// ---------------------------------------------------------------------------
#define BM 128
#define BNb 128
#define BK 16
#define SPAD 4
#define WROW (BNb + SPAD)

__global__ void __launch_bounds__(256, 2)
gemm_k(const float* __restrict__ A) {
    __shared__ float As[2][BK][BM + SPAD];
    __shared__ float Ws[2][BK][WROW];

    const int tid = threadIdx.x;
    const int tx = tid & 15;
    const int ty = tid >> 4;
    const int m0 = blockIdx.y * BM;
    const int n0 = blockIdx.x * BNb;

    const int ar0 = ty * 4;
    const int bc0 = tx * 4;

    const int lrow0 = tid >> 2;          // 0..63
    const int lkv   = (tid & 3) * 4;     // 0,4,8,12
    const float* Aptr0 = A + (size_t)(m0 + lrow0) * CIN + lkv;
    const size_t row64 = (size_t)64 * CIN;

    const int wk0 = tid >> 5;            // 0..7
    const int wc0 = tid & 31;
    const int wk1 = wk0 + 8;             // 8..15
    const uint32_t ws_u = smem_u32(&Ws[0][0][0]);
    const float* wsrc0 = &g_wt[wk0][n0 + wc0 * 4];
    const float* wsrc1 = &g_wt[wk1][n0 + wc0 * 4];

    unsigned long long acc[8][4];
#pragma unroll
    for (int i = 0; i < 8; i++)
#pragma unroll
        for (int j = 0; j < 4; j++) acc[i][j] = 0ULL;

    auto load_W = [&](int buf, int k0) {
        const uint32_t base = ws_u + (uint32_t)buf * (BK * WROW * 4);
        cp_async16(base + (wk0 * WROW + wc0 * 4) * 4, wsrc0 + (size_t)k0 * COUT);
        cp_async16(base + (wk1 * WROW + wc0 * 4) * 4, wsrc1 + (size_t)k0 * COUT);
        asm volatile("cp.async.commit_group;" ::: "memory");
    };
    auto store_A = [&](int buf, float4 ra0, float4 ra1) {
        As[buf][lkv + 0][lrow0] = ra0.x; As[buf][lkv + 1][lrow0] = ra0.y;
        As[buf][lkv + 2][lrow0] = ra0.z; As[buf][lkv + 3][lrow0] = ra0.w;
        As[buf][lkv + 0][lrow0 + 64] = ra1.x; As[buf][lkv + 1][lrow0 + 64] = ra1.y;
        As[buf][lkv + 2][lrow0 + 64] = ra1.z; As[buf][lkv + 3][lrow0 + 64] = ra1.w;
    };
    auto compute = [&](int buf) {
#pragma unroll
        for (int kk = 0; kk < BK; kk++) {
            float4 a0 = *reinterpret_cast<const float4*>(&As[buf][kk][ar0]);
            float4 a1 = *reinterpret_cast<const float4*>(&As[buf][kk][ar0 + 64]);
            float4 b0 = *reinterpret_cast<const float4*>(&Ws[buf][kk][bc0]);
            float4 b1 = *reinterpret_cast<const float4*>(&Ws[buf][kk][bc0 + 64]);
            unsigned long long bp[4];
            bp[0] = *reinterpret_cast<unsigned long long*>(&b0.x);
            bp[1] = *reinterpret_cast<unsigned long long*>(&b0.z);
            bp[2] = *reinterpret_cast<unsigned long long*>(&b1.x);
            bp[3] = *reinterpret_cast<unsigned long long*>(&b1.z);
            const float a[8] = {a0.x, a0.y, a0.z, a0.w, a1.x, a1.y, a1.z, a1.w};
#pragma unroll
            for (int i = 0; i < 8; i++) {
                const unsigned long long ap = pack_dup(a[i]);
#pragma unroll
                for (int jp = 0; jp < 4; jp++)
                    fma2(acc[i][jp], ap, bp[jp]);
            }
        }
    };

    // ---- prologue: stage 0 -> buffer 0
    {
        load_W(0, 0);
        float4 ra0 = *reinterpret_cast<const float4*>(Aptr0);
        float4 ra1 = *reinterpret_cast<const float4*>(Aptr0 + row64);
        store_A(0, ra0, ra1);
    }
    asm volatile("cp.async.wait_group 0;" ::: "memory");
    __syncthreads();

    // ---- main loop: 16 iterations x 2 stages, fixed buffer roles
    const int NPAIR = CIN / (2 * BK);    // 16
#pragma unroll 1
    for (int p = 0; p < NPAIR; p++) {
        const int k_even = 2 * p * BK;
        const int k_odd  = k_even + BK;

        {
            load_W(1, k_odd);
            float4 ra0 = *reinterpret_cast<const float4*>(Aptr0 + k_odd);
            float4 ra1 = *reinterpret_cast<const float4*>(Aptr0 + row64 + k_odd);
            compute(0);
            store_A(1, ra0, ra1);
            asm volatile("cp.async.wait_group 0;" ::: "memory");
            __syncthreads();
        }

        if (p + 1 < NPAIR) {
            const int k_next = k_odd + BK;
            load_W(0, k_next);
            float4 ra0 = *reinterpret_cast<const float4*>(Aptr0 + k_next);
            float4 ra1 = *reinterpret_cast<const float4*>(Aptr0 + row64 + k_next);
            compute(1);
            store_A(0, ra0, ra1);
            asm volatile("cp.async.wait_group 0;" ::: "memory");
            __syncthreads();
        } else {
            compute(1);
        }
    }

    float acc_f[8][8];
#pragma unroll
    for (int i = 0; i < 8; i++)
#pragma unroll
        for (int jp = 0; jp < 4; jp++) {
            float2 v = unpack2(acc[i][jp]);
            acc_f[i][2 * jp + 0] = v.x;
            acc_f[i][2 * jp + 1] = v.y;
        }

    // ---- store C tile
#pragma unroll
    for (int ih = 0; ih < 2; ih++) {
#pragma unroll
        for (int i = 0; i < 4; i++) {
            const size_t m = (size_t)(m0 + ih * 64 + ar0 + i);
            const int ia = ih * 4 + i;
            float4 v0 = make_float4(acc_f[ia][0], acc_f[ia][1], acc_f[ia][2], acc_f[ia][3]);
            float4 v1 = make_float4(acc_f[ia][4], acc_f[ia][5], acc_f[ia][6], acc_f[ia][7]);
            *reinterpret_cast<float4*>(&g_y[m * COUT + n0 + bc0])      = v0;
            *reinterpret_cast<float4*>(&g_y[m * COUT + n0 + 64 + bc0]) = v1;
        }
    }

    // ---- fused BN partial stats (deterministic tree; reuse smem)
    __syncthreads();
    float* sred = &As[0][0][0];   // [16][128]
    float* qred = &As[1][0][0];   // [16][128]

    float s8[8], q8[8];
#pragma unroll
    for (int j = 0; j < 8; j++) { s8[j] = 0.0f; q8[j] = 0.0f; }
#pragma unroll
    for (int i = 0; i < 8; i++)
#pragma unroll
        for (int j = 0; j < 8; j++) {
            float v = acc_f[i][j];
            s8[j] += v;
            q8[j] = fmaf(v, v, q8[j]);
        }
#pragma unroll
    for (int jh = 0; jh < 2; jh++)
#pragma unroll
        for (int j = 0; j < 4; j++) {
            int c = jh * 64 + bc0 + j;
            sred[ty * 128 + c] = s8[jh * 4 + j];
            qred[ty * 128 + c] = q8[jh * 4 + j];
        }
    __syncthreads();

    if (tid < 128) {
        float s = 0.0f, q = 0.0f;
#pragma unroll
        for (int k = 0; k < 16; k++) {
            s += sred[k * 128 + tid];
            q += qred[k * 128 + tid];
        }
        g_psum[(size_t)blockIdx.y * COUT + n0 + tid] = s;
        g_psq [(size_t)blockIdx.y * COUT + n0 + tid] = q;
    }
}

// ---------------------------------------------------------------------------
// BN stats stage A: 64 blocks x 512 threads, coalesced (measured ~8us).
// ---------------------------------------------------------------------------
__global__ void __launch_bounds__(COUT)
stats2a_k() {
    const int o = threadIdx.x;
    const int b = blockIdx.x;
    float s = 0.0f, sq = 0.0f;
#pragma unroll
    for (int i = 0; i < NPART / NP2; i++) {
        s  += g_psum[(b * (NPART / NP2) + i) * COUT + o];
        sq += g_psq [(b * (NPART / NP2) + i) * COUT + o];
    }
    g_psum2[b * COUT + o] = s;
    g_psq2 [b * COUT + o] = sq;
}

// Stage B: finalize mean / rstd per channel. 512 threads, one channel each,
// scalar coalesced loads (the measured-best R10 shape; the 256-thread float2
// variant regressed 8.4 -> 12us by doubling the per-thread chain).
__global__ void __launch_bounds__(COUT)
stats2b_k() {
    const int o = threadIdx.x;
    float s = 0.0f, sq = 0.0f;
#pragma unroll
    for (int i = 0; i < NP2; i++) {
        s  += g_psum2[i * COUT + o];
        sq += g_psq2 [i * COUT + o];
    }
    const float inv_m = 1.0f / (float)M_TOTAL;
    float mean = s * inv_m;
    float var  = sq * inv_m - mean * mean;
    g_mean[o] = mean;
    g_rstd[o] = rsqrtf(var + 1e-5f);
}

// ---------------------------------------------------------------------------
// Fused BN + multistep LIF + output store (vec8 per thread; measured 74us).
// ---------------------------------------------------------------------------
__device__ __forceinline__ void lif_lane(float raw, float mean, float rstd,
                                         float ga, float be, float& v, float& sp) {
    float xt = (raw - mean) * rstd;
    xt = xt * ga + be;
    v = v + (xt - v) * 0.5f;
    sp = (v >= 1.0f) ? 1.0f : 0.0f;
    v = v * (1.0f - sp);
}

__global__ void __launch_bounds__(256)
lif_k(const float* __restrict__ gamma, const float* __restrict__ beta,
      float* __restrict__ out) {
    const int idx8 = blockIdx.x * blockDim.x + threadIdx.x;
    const int total8 = B_BATCH * N_SEQ * COUT / 8;
    if (idx8 >= total8) return;
    const int idx = idx8 * 2;
    const int o4 = (idx & (COUT / 4 - 1)) * 4;

    const float4 meanA = *reinterpret_cast<const float4*>(&g_mean[o4]);
    const float4 meanB = *reinterpret_cast<const float4*>(&g_mean[o4 + 4]);
    const float4 rstdA = *reinterpret_cast<const float4*>(&g_rstd[o4]);
    const float4 rstdB = *reinterpret_cast<const float4*>(&g_rstd[o4 + 4]);
    const float4 gaA   = *reinterpret_cast<const float4*>(&gamma[o4]);
    const float4 gaB   = *reinterpret_cast<const float4*>(&gamma[o4 + 4]);
    const float4 beA   = *reinterpret_cast<const float4*>(&beta[o4]);
    const float4 beB   = *reinterpret_cast<const float4*>(&beta[o4 + 4]);

    const size_t stride4 = (size_t)B_BATCH * N_SEQ * COUT / 4;
    const float4* yv = reinterpret_cast<const float4*>(g_y);
    float4* ov = reinterpret_cast<float4*>(out);

    float4 rA[T_STEPS], rB[T_STEPS];
#pragma unroll
    for (int t = 0; t < T_STEPS; t++) {
        const size_t off = (size_t)idx + (size_t)t * stride4;
        rA[t] = yv[off];
        rB[t] = yv[off + 1];
    }

    float vA0 = 0, vA1 = 0, vA2 = 0, vA3 = 0;
    float vB0 = 0, vB1 = 0, vB2 = 0, vB3 = 0;
#pragma unroll
    for (int t = 0; t < T_STEPS; t++) {
        const size_t off = (size_t)idx + (size_t)t * stride4;
        float4 spA, spB;
        lif_lane(rA[t].x, meanA.x, rstdA.x, gaA.x, beA.x, vA0, spA.x);
        lif_lane(rA[t].y, meanA.y, rstdA.y, gaA.y, beA.y, vA1, spA.y);
        lif_lane(rA[t].z, meanA.z, rstdA.z, gaA.z, beA.z, vA2, spA.z);
        lif_lane(rA[t].w, meanA.w, rstdA.w, gaA.w, beA.w, vA3, spA.w);
        lif_lane(rB[t].x, meanB.x, rstdB.x, gaB.x, beB.x, vB0, spB.x);
        lif_lane(rB[t].y, meanB.y, rstdB.y, gaB.y, beB.y, vB1, spB.y);
        lif_lane(rB[t].z, meanB.z, rstdB.z, gaB.z, beB.z, vB2, spB.z);
        lif_lane(rB[t].w, meanB.w, rstdB.w, gaB.w, beB.w, vB3, spB.w);
        ov[off]     = spA;
        ov[off + 1] = spB;
    }
}

// ---------------------------------------------------------------------------
extern "C" void kernel_launch(void* const* d_in, const int* in_sizes, int n_in,
                              void* d_out, int out_size) {
    const float* x     = (const float*)d_in[0];
    const float* W     = (const float*)d_in[1];
    const float* gamma = (const float*)d_in[2];
    const float* beta  = (const float*)d_in[3];
    float* out = (float*)d_out;

    dim3 wt_grid(COUT / 32, CIN / 32);
    wt_k<<<wt_grid, 256>>>(W);

    dim3 gemm_grid(COUT / BNb, M_TOTAL / BM);    // (4, 1024)
    gemm_k<<<gemm_grid, 256>>>(x);

    stats2a_k<<<NP2, COUT>>>();
    stats2b_k<<<1, COUT>>>();

    const int total8 = B_BATCH * N_SEQ * COUT / 8;
    lif_k<<<(total8 + 255) / 256, 256>>>(gamma, beta, out);
}

// round 14
// speedup vs baseline: 1.1402x; 1.0009x over previous
#include <cuda_runtime.h>
#include <cstdint>

// Problem constants (fixed shapes from reference setup_inputs)
#define T_STEPS 4
#define B_BATCH 32            // TB / T = 128/4
#define N_SEQ   1024
#define CIN     512
#define COUT    512
#define M_TOTAL (T_STEPS * B_BATCH * N_SEQ)   // 131072 rows

// Scratch in device globals (no allocations allowed)
__device__ float g_y[(size_t)M_TOTAL * COUT];      // 268 MB GEMM output
__device__ float g_wt[CIN][COUT];                   // W transposed: [k][o], 1 MB
#define NPART 1024
#define NP2   64
__device__ float g_psum[NPART * COUT];
__device__ float g_psq [NPART * COUT];
__device__ float g_psum2[NP2 * COUT];
__device__ float g_psq2 [NP2 * COUT];
__device__ float g_mean[COUT];
__device__ float g_rstd[COUT];

// ---------------------------------------------------------------------------
// Packed f32x2 helpers (per-lane bitwise-identical to scalar fmaf).
// ---------------------------------------------------------------------------
__device__ __forceinline__ unsigned long long pack_dup(float a) {
    unsigned long long u;
    asm("mov.b64 %0, {%1, %1};" : "=l"(u) : "f"(a));
    return u;
}
__device__ __forceinline__ void fma2(unsigned long long& acc,
                                     unsigned long long a,
                                     unsigned long long b) {
    asm("fma.rn.f32x2 %0, %1, %2, %0;" : "+l"(acc) : "l"(a), "l"(b));
}
__device__ __forceinline__ float2 unpack2(unsigned long long u) {
    float lo, hi;
    asm("mov.b64 {%0, %1}, %2;" : "=f"(lo), "=f"(hi) : "l"(u));
    return make_float2(lo, hi);
}
__device__ __forceinline__ uint32_t smem_u32(const void* p) {
    uint32_t a;
    asm("{ .reg .u64 t; cvta.to.shared.u64 t, %1; cvt.u32.u64 %0, t; }" : "=r"(a) : "l"(p));
    return a;
}
__device__ __forceinline__ void cp_async16(uint32_t dst, const void* src) {
    asm volatile("cp.async.cg.shared.global [%0], [%1], 16;" :: "r"(dst), "l"(src) : "memory");
}

// ---------------------------------------------------------------------------
// Tiled transpose: g_wt[k][o] = W[o][k].
// ---------------------------------------------------------------------------
__global__ void __launch_bounds__(256)
wt_k(const float* __restrict__ W) {
    __shared__ float t[32][33];
    const int bo = blockIdx.x * 32;
    const int bk = blockIdx.y * 32;
    const int lx = threadIdx.x & 31;
    const int ly = threadIdx.x >> 5;
#pragma unroll
    for (int i = 0; i < 4; i++)
        t[ly + 8 * i][lx] = W[(size_t)(bo + ly + 8 * i) * CIN + bk + lx];
    __syncthreads();
#pragma unroll
    for (int i = 0; i < 4; i++)
        g_wt[bk + ly + 8 * i][bo + lx] = t[lx][ly + 8 * i];
}

// ---------------------------------------------------------------------------
// SGEMM: C[m,o] = sum_k A[m,k]*W[o,k], k strictly sequential fp32 per output
// (must reproduce reference rounding; tensor-core adder trees flip spikes).
// 128x128x16 tile, 256 threads, 8x8/thread, double-buffered smem, stage loop
// manually unrolled x2 (compile-time smem addressing).
// NEW: warp thread grid reshaped 16x2 -> 8x4 (tx,ty). Per warp per kk smem
// traffic drops 576B -> 384B (a:4 distinct, b:8 distinct 16B lines), taking
// the SM's 128B/cyc smem crossbar from 112% oversubscribed to 75%.
// Ownership remap only — each output's k-order unchanged -> bitwise identical.
// ---------------------------------------------------------------------------
#define BM 128
#define BNb 128
#define BK 16
#define SPAD 4
#define WROW (BNb + SPAD)

__global__ void __launch_bounds__(256, 2)
gemm_k(const float* __restrict__ A) {
    __shared__ float As[2][BK][BM + SPAD];
    __shared__ float Ws[2][BK][WROW];

    const int tid = threadIdx.x;
    // warp-internal 8x4 grid: warp w covers tx in {8*(w&1)..+7}, ty in {4*(w>>1)..+3}
    const int lane = tid & 31;
    const int w    = tid >> 5;
    const int tx = (lane & 7) | ((w & 1) << 3);    // 0..15
    const int ty = (lane >> 3) | ((w >> 1) << 2);  // 0..15
    const int m0 = blockIdx.y * BM;
    const int n0 = blockIdx.x * BNb;

    const int ar0 = ty * 4;
    const int bc0 = tx * 4;

    const int lrow0 = tid >> 2;          // 0..63
    const int lkv   = (tid & 3) * 4;     // 0,4,8,12
    const float* Aptr0 = A + (size_t)(m0 + lrow0) * CIN + lkv;
    const size_t row64 = (size_t)64 * CIN;

    const int wk0 = tid >> 5;            // 0..7
    const int wc0 = tid & 31;
    const int wk1 = wk0 + 8;             // 8..15
    const uint32_t ws_u = smem_u32(&Ws[0][0][0]);
    const float* wsrc0 = &g_wt[wk0][n0 + wc0 * 4];
    const float* wsrc1 = &g_wt[wk1][n0 + wc0 * 4];

    unsigned long long acc[8][4];
#pragma unroll
    for (int i = 0; i < 8; i++)
#pragma unroll
        for (int j = 0; j < 4; j++) acc[i][j] = 0ULL;

    auto load_W = [&](int buf, int k0) {
        const uint32_t base = ws_u + (uint32_t)buf * (BK * WROW * 4);
        cp_async16(base + (wk0 * WROW + wc0 * 4) * 4, wsrc0 + (size_t)k0 * COUT);
        cp_async16(base + (wk1 * WROW + wc0 * 4) * 4, wsrc1 + (size_t)k0 * COUT);
        asm volatile("cp.async.commit_group;" ::: "memory");
    };
    auto store_A = [&](int buf, float4 ra0, float4 ra1) {
        As[buf][lkv + 0][lrow0] = ra0.x; As[buf][lkv + 1][lrow0] = ra0.y;
        As[buf][lkv + 2][lrow0] = ra0.z; As[buf][lkv + 3][lrow0] = ra0.w;
        As[buf][lkv + 0][lrow0 + 64] = ra1.x; As[buf][lkv + 1][lrow0 + 64] = ra1.y;
        As[buf][lkv + 2][lrow0 + 64] = ra1.z; As[buf][lkv + 3][lrow0 + 64] = ra1.w;
    };
    auto compute = [&](int buf) {
#pragma unroll
        for (int kk = 0; kk < BK; kk++) {
            float4 a0 = *reinterpret_cast<const float4*>(&As[buf][kk][ar0]);
            float4 a1 = *reinterpret_cast<const float4*>(&As[buf][kk][ar0 + 64]);
            float4 b0 = *reinterpret_cast<const float4*>(&Ws[buf][kk][bc0]);
            float4 b1 = *reinterpret_cast<const float4*>(&Ws[buf][kk][bc0 + 64]);
            unsigned long long bp[4];
            bp[0] = *reinterpret_cast<unsigned long long*>(&b0.x);
            bp[1] = *reinterpret_cast<unsigned long long*>(&b0.z);
            bp[2] = *reinterpret_cast<unsigned long long*>(&b1.x);
            bp[3] = *reinterpret_cast<unsigned long long*>(&b1.z);
            const float a[8] = {a0.x, a0.y, a0.z, a0.w, a1.x, a1.y, a1.z, a1.w};
#pragma unroll
            for (int i = 0; i < 8; i++) {
                const unsigned long long ap = pack_dup(a[i]);
#pragma unroll
                for (int jp = 0; jp < 4; jp++)
                    fma2(acc[i][jp], ap, bp[jp]);
            }
        }
    };

    // ---- prologue: stage 0 -> buffer 0
    {
        load_W(0, 0);
        float4 ra0 = *reinterpret_cast<const float4*>(Aptr0);
        float4 ra1 = *reinterpret_cast<const float4*>(Aptr0 + row64);
        store_A(0, ra0, ra1);
    }
    asm volatile("cp.async.wait_group 0;" ::: "memory");
    __syncthreads();

    // ---- main loop: 16 iterations x 2 stages, fixed buffer roles
    const int NPAIR = CIN / (2 * BK);    // 16
#pragma unroll 1
    for (int p = 0; p < NPAIR; p++) {
        const int k_even = 2 * p * BK;
        const int k_odd  = k_even + BK;

        {
            load_W(1, k_odd);
            float4 ra0 = *reinterpret_cast<const float4*>(Aptr0 + k_odd);
            float4 ra1 = *reinterpret_cast<const float4*>(Aptr0 + row64 + k_odd);
            compute(0);
            store_A(1, ra0, ra1);
            asm volatile("cp.async.wait_group 0;" ::: "memory");
            __syncthreads();
        }

        if (p + 1 < NPAIR) {
            const int k_next = k_odd + BK;
            load_W(0, k_next);
            float4 ra0 = *reinterpret_cast<const float4*>(Aptr0 + k_next);
            float4 ra1 = *reinterpret_cast<const float4*>(Aptr0 + row64 + k_next);
            compute(1);
            store_A(0, ra0, ra1);
            asm volatile("cp.async.wait_group 0;" ::: "memory");
            __syncthreads();
        } else {
            compute(1);
        }
    }

    float acc_f[8][8];
#pragma unroll
    for (int i = 0; i < 8; i++)
#pragma unroll
        for (int jp = 0; jp < 4; jp++) {
            float2 v = unpack2(acc[i][jp]);
            acc_f[i][2 * jp + 0] = v.x;
            acc_f[i][2 * jp + 1] = v.y;
        }

    // ---- store C tile
#pragma unroll
    for (int ih = 0; ih < 2; ih++) {
#pragma unroll
        for (int i = 0; i < 4; i++) {
            const size_t m = (size_t)(m0 + ih * 64 + ar0 + i);
            const int ia = ih * 4 + i;
            float4 v0 = make_float4(acc_f[ia][0], acc_f[ia][1], acc_f[ia][2], acc_f[ia][3]);
            float4 v1 = make_float4(acc_f[ia][4], acc_f[ia][5], acc_f[ia][6], acc_f[ia][7]);
            *reinterpret_cast<float4*>(&g_y[m * COUT + n0 + bc0])      = v0;
            *reinterpret_cast<float4*>(&g_y[m * COUT + n0 + 64 + bc0]) = v1;
        }
    }

    // ---- fused BN partial stats (deterministic tree; reuse smem)
    __syncthreads();
    float* sred = &As[0][0][0];   // [16][128]
    float* qred = &As[1][0][0];   // [16][128]

    float s8[8], q8[8];
#pragma unroll
    for (int j = 0; j < 8; j++) { s8[j] = 0.0f; q8[j] = 0.0f; }
#pragma unroll
    for (int i = 0; i < 8; i++)
#pragma unroll
        for (int j = 0; j < 8; j++) {
            float v = acc_f[i][j];
            s8[j] += v;
            q8[j] = fmaf(v, v, q8[j]);
        }
#pragma unroll
    for (int jh = 0; jh < 2; jh++)
#pragma unroll
        for (int j = 0; j < 4; j++) {
            int c = jh * 64 + bc0 + j;
            sred[ty * 128 + c] = s8[jh * 4 + j];
            qred[ty * 128 + c] = q8[jh * 4 + j];
        }
    __syncthreads();

    if (tid < 128) {
        float s = 0.0f, q = 0.0f;
#pragma unroll
        for (int k = 0; k < 16; k++) {
            s += sred[k * 128 + tid];
            q += qred[k * 128 + tid];
        }
        g_psum[(size_t)blockIdx.y * COUT + n0 + tid] = s;
        g_psq [(size_t)blockIdx.y * COUT + n0 + tid] = q;
    }
}

// ---------------------------------------------------------------------------
// BN stats stage A: 64 blocks x 512 threads, coalesced (measured ~8us).
// ---------------------------------------------------------------------------
__global__ void __launch_bounds__(COUT)
stats2a_k() {
    const int o = threadIdx.x;
    const int b = blockIdx.x;
    float s = 0.0f, sq = 0.0f;
#pragma unroll
    for (int i = 0; i < NPART / NP2; i++) {
        s  += g_psum[(b * (NPART / NP2) + i) * COUT + o];
        sq += g_psq [(b * (NPART / NP2) + i) * COUT + o];
    }
    g_psum2[b * COUT + o] = s;
    g_psq2 [b * COUT + o] = sq;
}

// Stage B: finalize mean / rstd (512 threads, measured-best shape).
__global__ void __launch_bounds__(COUT)
stats2b_k() {
    const int o = threadIdx.x;
    float s = 0.0f, sq = 0.0f;
#pragma unroll
    for (int i = 0; i < NP2; i++) {
        s  += g_psum2[i * COUT + o];
        sq += g_psq2 [i * COUT + o];
    }
    const float inv_m = 1.0f / (float)M_TOTAL;
    float mean = s * inv_m;
    float var  = sq * inv_m - mean * mean;
    g_mean[o] = mean;
    g_rstd[o] = rsqrtf(var + 1e-5f);
}

// ---------------------------------------------------------------------------
// Fused BN + multistep LIF + output store (vec8 per thread; measured 74us).
// ---------------------------------------------------------------------------
__device__ __forceinline__ void lif_lane(float raw, float mean, float rstd,
                                         float ga, float be, float& v, float& sp) {
    float xt = (raw - mean) * rstd;
    xt = xt * ga + be;
    v = v + (xt - v) * 0.5f;
    sp = (v >= 1.0f) ? 1.0f : 0.0f;
    v = v * (1.0f - sp);
}

__global__ void __launch_bounds__(256)
lif_k(const float* __restrict__ gamma, const float* __restrict__ beta,
      float* __restrict__ out) {
    const int idx8 = blockIdx.x * blockDim.x + threadIdx.x;
    const int total8 = B_BATCH * N_SEQ * COUT / 8;
    if (idx8 >= total8) return;
    const int idx = idx8 * 2;
    const int o4 = (idx & (COUT / 4 - 1)) * 4;

    const float4 meanA = *reinterpret_cast<const float4*>(&g_mean[o4]);
    const float4 meanB = *reinterpret_cast<const float4*>(&g_mean[o4 + 4]);
    const float4 rstdA = *reinterpret_cast<const float4*>(&g_rstd[o4]);
    const float4 rstdB = *reinterpret_cast<const float4*>(&g_rstd[o4 + 4]);
    const float4 gaA   = *reinterpret_cast<const float4*>(&gamma[o4]);
    const float4 gaB   = *reinterpret_cast<const float4*>(&gamma[o4 + 4]);
    const float4 beA   = *reinterpret_cast<const float4*>(&beta[o4]);
    const float4 beB   = *reinterpret_cast<const float4*>(&beta[o4 + 4]);

    const size_t stride4 = (size_t)B_BATCH * N_SEQ * COUT / 4;
    const float4* yv = reinterpret_cast<const float4*>(g_y);
    float4* ov = reinterpret_cast<float4*>(out);

    float4 rA[T_STEPS], rB[T_STEPS];
#pragma unroll
    for (int t = 0; t < T_STEPS; t++) {
        const size_t off = (size_t)idx + (size_t)t * stride4;
        rA[t] = yv[off];
        rB[t] = yv[off + 1];
    }

    float vA0 = 0, vA1 = 0, vA2 = 0, vA3 = 0;
    float vB0 = 0, vB1 = 0, vB2 = 0, vB3 = 0;
#pragma unroll
    for (int t = 0; t < T_STEPS; t++) {
        const size_t off = (size_t)idx + (size_t)t * stride4;
        float4 spA, spB;
        lif_lane(rA[t].x, meanA.x, rstdA.x, gaA.x, beA.x, vA0, spA.x);
        lif_lane(rA[t].y, meanA.y, rstdA.y, gaA.y, beA.y, vA1, spA.y);
        lif_lane(rA[t].z, meanA.z, rstdA.z, gaA.z, beA.z, vA2, spA.z);
        lif_lane(rA[t].w, meanA.w, rstdA.w, gaA.w, beA.w, vA3, spA.w);
        lif_lane(rB[t].x, meanB.x, rstdB.x, gaB.x, beB.x, vB0, spB.x);
        lif_lane(rB[t].y, meanB.y, rstdB.y, gaB.y, beB.y, vB1, spB.y);
        lif_lane(rB[t].z, meanB.z, rstdB.z, gaB.z, beB.z, vB2, spB.z);
        lif_lane(rB[t].w, meanB.w, rstdB.w, gaB.w, beB.w, vB3, spB.w);
        ov[off]     = spA;
        ov[off + 1] = spB;
    }
}

// ---------------------------------------------------------------------------
extern "C" void kernel_launch(void* const* d_in, const int* in_sizes, int n_in,
                              void* d_out, int out_size) {
    const float* x     = (const float*)d_in[0];
    const float* W     = (const float*)d_in[1];
    const float* gamma = (const float*)d_in[2];
    const float* beta  = (const float*)d_in[3];
    float* out = (float*)d_out;

    dim3 wt_grid(COUT / 32, CIN / 32);
    wt_k<<<wt_grid, 256>>>(W);

    dim3 gemm_grid(COUT / BNb, M_TOTAL / BM);    // (4, 1024)
    gemm_k<<<gemm_grid, 256>>>(x);

    stats2a_k<<<NP2, COUT>>>();
    stats2b_k<<<1, COUT>>>();

    const int total8 = B_BATCH * N_SEQ * COUT / 8;
    lif_k<<<(total8 + 255) / 256, 256>>>(gamma, beta, out);
}

// round 15
// speedup vs baseline: 1.1413x; 1.0010x over previous
#include <cuda_runtime.h>
#include <cstdint>

// Problem constants (fixed shapes from reference setup_inputs)
#define T_STEPS 4
#define B_BATCH 32            // TB / T = 128/4
#define N_SEQ   1024
#define CIN     512
#define COUT    512
#define M_TOTAL (T_STEPS * B_BATCH * N_SEQ)   // 131072 rows

// Scratch in device globals (no allocations allowed)
__device__ float g_y[(size_t)M_TOTAL * COUT];      // 268 MB GEMM output
__device__ float g_wt[CIN][COUT];                   // W transposed: [k][o], 1 MB
#define NPART 1024
#define NP2   64
__device__ float g_psum[NPART * COUT];
__device__ float g_psq [NPART * COUT];
__device__ float g_psum2[NP2 * COUT];
__device__ float g_psq2 [NP2 * COUT];
__device__ float g_mean[COUT];
__device__ float g_rstd[COUT];
__device__ unsigned int g_ticket;                   // last-block-finalize counter

// ---------------------------------------------------------------------------
// Packed f32x2 helpers (per-lane bitwise-identical to scalar fmaf).
// ---------------------------------------------------------------------------
__device__ __forceinline__ unsigned long long pack_dup(float a) {
    unsigned long long u;
    asm("mov.b64 %0, {%1, %1};" : "=l"(u) : "f"(a));
    return u;
}
__device__ __forceinline__ void fma2(unsigned long long& acc,
                                     unsigned long long a,
                                     unsigned long long b) {
    asm("fma.rn.f32x2 %0, %1, %2, %0;" : "+l"(acc) : "l"(a), "l"(b));
}
__device__ __forceinline__ float2 unpack2(unsigned long long u) {
    float lo, hi;
    asm("mov.b64 {%0, %1}, %2;" : "=f"(lo), "=f"(hi) : "l"(u));
    return make_float2(lo, hi);
}
__device__ __forceinline__ uint32_t smem_u32(const void* p) {
    uint32_t a;
    asm("{ .reg .u64 t; cvta.to.shared.u64 t, %1; cvt.u32.u64 %0, t; }" : "=r"(a) : "l"(p));
    return a;
}
__device__ __forceinline__ void cp_async16(uint32_t dst, const void* src) {
    asm volatile("cp.async.cg.shared.global [%0], [%1], 16;" :: "r"(dst), "l"(src) : "memory");
}

// ---------------------------------------------------------------------------
// Tiled transpose: g_wt[k][o] = W[o][k]. Also resets the stats ticket
// (wt_k strictly precedes the stats kernel on the stream).
// ---------------------------------------------------------------------------
__global__ void __launch_bounds__(256)
wt_k(const float* __restrict__ W) {
    __shared__ float t[32][33];
    if (blockIdx.x == 0 && blockIdx.y == 0 && threadIdx.x == 0) g_ticket = 0u;
    const int bo = blockIdx.x * 32;
    const int bk = blockIdx.y * 32;
    const int lx = threadIdx.x & 31;
    const int ly = threadIdx.x >> 5;
#pragma unroll
    for (int i = 0; i < 4; i++)
        t[ly + 8 * i][lx] = W[(size_t)(bo + ly + 8 * i) * CIN + bk + lx];
    __syncthreads();
#pragma unroll
    for (int i = 0; i < 4; i++)
        g_wt[bk + ly + 8 * i][bo + lx] = t[lx][ly + 8 * i];
}

// ---------------------------------------------------------------------------
// SGEMM: C[m,o] = sum_k A[m,k]*W[o,k], k strictly sequential fp32 per output
// (must reproduce reference rounding; tensor-core adder trees flip spikes).
// 128x128x16 tile, 256 threads, 8x8/thread, double-buffered smem, stage loop
// manually unrolled x2 (compile-time smem addressing). Measured 93% of the
// fp32 datapath peak — structural floor under the exact-arithmetic constraint.
// BN partials fused in epilogue (deterministic tree).
// ---------------------------------------------------------------------------
#define BM 128
#define BNb 128
#define BK 16
#define SPAD 4
#define WROW (BNb + SPAD)

__global__ void __launch_bounds__(256, 2)
gemm_k(const float* __restrict__ A) {
    __shared__ float As[2][BK][BM + SPAD];
    __shared__ float Ws[2][BK][WROW];

    const int tid = threadIdx.x;
    const int lane = tid & 31;
    const int w    = tid >> 5;
    const int tx = (lane & 7) | ((w & 1) << 3);    // 0..15
    const int ty = (lane >> 3) | ((w >> 1) << 2);  // 0..15
    const int m0 = blockIdx.y * BM;
    const int n0 = blockIdx.x * BNb;

    const int ar0 = ty * 4;
    const int bc0 = tx * 4;

    const int lrow0 = tid >> 2;          // 0..63
    const int lkv   = (tid & 3) * 4;     // 0,4,8,12
    const float* Aptr0 = A + (size_t)(m0 + lrow0) * CIN + lkv;
    const size_t row64 = (size_t)64 * CIN;

    const int wk0 = tid >> 5;            // 0..7
    const int wc0 = tid & 31;
    const int wk1 = wk0 + 8;             // 8..15
    const uint32_t ws_u = smem_u32(&Ws[0][0][0]);
    const float* wsrc0 = &g_wt[wk0][n0 + wc0 * 4];
    const float* wsrc1 = &g_wt[wk1][n0 + wc0 * 4];

    unsigned long long acc[8][4];
#pragma unroll
    for (int i = 0; i < 8; i++)
#pragma unroll
        for (int j = 0; j < 4; j++) acc[i][j] = 0ULL;

    auto load_W = [&](int buf, int k0) {
        const uint32_t base = ws_u + (uint32_t)buf * (BK * WROW * 4);
        cp_async16(base + (wk0 * WROW + wc0 * 4) * 4, wsrc0 + (size_t)k0 * COUT);
        cp_async16(base + (wk1 * WROW + wc0 * 4) * 4, wsrc1 + (size_t)k0 * COUT);
        asm volatile("cp.async.commit_group;" ::: "memory");
    };
    auto store_A = [&](int buf, float4 ra0, float4 ra1) {
        As[buf][lkv + 0][lrow0] = ra0.x; As[buf][lkv + 1][lrow0] = ra0.y;
        As[buf][lkv + 2][lrow0] = ra0.z; As[buf][lkv + 3][lrow0] = ra0.w;
        As[buf][lkv + 0][lrow0 + 64] = ra1.x; As[buf][lkv + 1][lrow0 + 64] = ra1.y;
        As[buf][lkv + 2][lrow0 + 64] = ra1.z; As[buf][lkv + 3][lrow0 + 64] = ra1.w;
    };
    auto compute = [&](int buf) {
#pragma unroll
        for (int kk = 0; kk < BK; kk++) {
            float4 a0 = *reinterpret_cast<const float4*>(&As[buf][kk][ar0]);
            float4 a1 = *reinterpret_cast<const float4*>(&As[buf][kk][ar0 + 64]);
            float4 b0 = *reinterpret_cast<const float4*>(&Ws[buf][kk][bc0]);
            float4 b1 = *reinterpret_cast<const float4*>(&Ws[buf][kk][bc0 + 64]);
            unsigned long long bp[4];
            bp[0] = *reinterpret_cast<unsigned long long*>(&b0.x);
            bp[1] = *reinterpret_cast<unsigned long long*>(&b0.z);
            bp[2] = *reinterpret_cast<unsigned long long*>(&b1.x);
            bp[3] = *reinterpret_cast<unsigned long long*>(&b1.z);
            const float a[8] = {a0.x, a0.y, a0.z, a0.w, a1.x, a1.y, a1.z, a1.w};
#pragma unroll
            for (int i = 0; i < 8; i++) {
                const unsigned long long ap = pack_dup(a[i]);
#pragma unroll
                for (int jp = 0; jp < 4; jp++)
                    fma2(acc[i][jp], ap, bp[jp]);
            }
        }
    };

    // ---- prologue: stage 0 -> buffer 0
    {
        load_W(0, 0);
        float4 ra0 = *reinterpret_cast<const float4*>(Aptr0);
        float4 ra1 = *reinterpret_cast<const float4*>(Aptr0 + row64);
        store_A(0, ra0, ra1);
    }
    asm volatile("cp.async.wait_group 0;" ::: "memory");
    __syncthreads();

    // ---- main loop: 16 iterations x 2 stages, fixed buffer roles
    const int NPAIR = CIN / (2 * BK);    // 16
#pragma unroll 1
    for (int p = 0; p < NPAIR; p++) {
        const int k_odd = 2 * p * BK + BK;

        {
            load_W(1, k_odd);
            float4 ra0 = *reinterpret_cast<const float4*>(Aptr0 + k_odd);
            float4 ra1 = *reinterpret_cast<const float4*>(Aptr0 + row64 + k_odd);
            compute(0);
            store_A(1, ra0, ra1);
            asm volatile("cp.async.wait_group 0;" ::: "memory");
            __syncthreads();
        }

        if (p + 1 < NPAIR) {
            const int k_next = k_odd + BK;
            load_W(0, k_next);
            float4 ra0 = *reinterpret_cast<const float4*>(Aptr0 + k_next);
            float4 ra1 = *reinterpret_cast<const float4*>(Aptr0 + row64 + k_next);
            compute(1);
            store_A(0, ra0, ra1);
            asm volatile("cp.async.wait_group 0;" ::: "memory");
            __syncthreads();
        } else {
            compute(1);
        }
    }

    float acc_f[8][8];
#pragma unroll
    for (int i = 0; i < 8; i++)
#pragma unroll
        for (int jp = 0; jp < 4; jp++) {
            float2 v = unpack2(acc[i][jp]);
            acc_f[i][2 * jp + 0] = v.x;
            acc_f[i][2 * jp + 1] = v.y;
        }

    // ---- store C tile
#pragma unroll
    for (int ih = 0; ih < 2; ih++) {
#pragma unroll
        for (int i = 0; i < 4; i++) {
            const size_t m = (size_t)(m0 + ih * 64 + ar0 + i);
            const int ia = ih * 4 + i;
            float4 v0 = make_float4(acc_f[ia][0], acc_f[ia][1], acc_f[ia][2], acc_f[ia][3]);
            float4 v1 = make_float4(acc_f[ia][4], acc_f[ia][5], acc_f[ia][6], acc_f[ia][7]);
            *reinterpret_cast<float4*>(&g_y[m * COUT + n0 + bc0])      = v0;
            *reinterpret_cast<float4*>(&g_y[m * COUT + n0 + 64 + bc0]) = v1;
        }
    }

    // ---- fused BN partial stats (deterministic tree; reuse smem)
    __syncthreads();
    float* sred = &As[0][0][0];   // [16][128]
    float* qred = &As[1][0][0];   // [16][128]

    float s8[8], q8[8];
#pragma unroll
    for (int j = 0; j < 8; j++) { s8[j] = 0.0f; q8[j] = 0.0f; }
#pragma unroll
    for (int i = 0; i < 8; i++)
#pragma unroll
        for (int j = 0; j < 8; j++) {
            float v = acc_f[i][j];
            s8[j] += v;
            q8[j] = fmaf(v, v, q8[j]);
        }
#pragma unroll
    for (int jh = 0; jh < 2; jh++)
#pragma unroll
        for (int j = 0; j < 4; j++) {
            int c = jh * 64 + bc0 + j;
            sred[ty * 128 + c] = s8[jh * 4 + j];
            qred[ty * 128 + c] = q8[jh * 4 + j];
        }
    __syncthreads();

    if (tid < 128) {
        float s = 0.0f, q = 0.0f;
#pragma unroll
        for (int k = 0; k < 16; k++) {
            s += sred[k * 128 + tid];
            q += qred[k * 128 + tid];
        }
        g_psum[(size_t)blockIdx.y * COUT + n0 + tid] = s;
        g_psq [(size_t)blockIdx.y * COUT + n0 + tid] = q;
    }
}

// ---------------------------------------------------------------------------
// Fused BN stats: 64 blocks x 512 threads. Each block reduces its 16 partial
// rows (coalesced, same order as before) -> g_psum2/g_psq2; the LAST block to
// finish (fence + ticket) additionally finalizes mean/rstd by summing the 64
// partials in fixed index order — bitwise-identical result regardless of
// which block runs last. Saves one kernel launch + grid drain.
// ---------------------------------------------------------------------------
__global__ void __launch_bounds__(COUT)
stats_k() {
    const int o = threadIdx.x;
    const int b = blockIdx.x;
    float s = 0.0f, sq = 0.0f;
#pragma unroll
    for (int i = 0; i < NPART / NP2; i++) {
        s  += g_psum[(b * (NPART / NP2) + i) * COUT + o];
        sq += g_psq [(b * (NPART / NP2) + i) * COUT + o];
    }
    g_psum2[b * COUT + o] = s;
    g_psq2 [b * COUT + o] = sq;

    // last-block finalize
    __threadfence();
    __shared__ unsigned int s_last;
    __syncthreads();
    if (o == 0) {
        unsigned int t = atomicAdd(&g_ticket, 1u);
        s_last = (t == NP2 - 1) ? 1u : 0u;
    }
    __syncthreads();
    if (s_last) {
        float fs = 0.0f, fq = 0.0f;
#pragma unroll
        for (int i = 0; i < NP2; i++) {
            fs += g_psum2[i * COUT + o];
            fq += g_psq2 [i * COUT + o];
        }
        const float inv_m = 1.0f / (float)M_TOTAL;
        float mean = fs * inv_m;
        float var  = fq * inv_m - mean * mean;
        g_mean[o] = mean;
        g_rstd[o] = rsqrtf(var + 1e-5f);
    }
}

// ---------------------------------------------------------------------------
// Fused BN + multistep LIF + output store (vec8 per thread; measured 74us).
// ---------------------------------------------------------------------------
__device__ __forceinline__ void lif_lane(float raw, float mean, float rstd,
                                         float ga, float be, float& v, float& sp) {
    float xt = (raw - mean) * rstd;
    xt = xt * ga + be;
    v = v + (xt - v) * 0.5f;
    sp = (v >= 1.0f) ? 1.0f : 0.0f;
    v = v * (1.0f - sp);
}

__global__ void __launch_bounds__(256)
lif_k(const float* __restrict__ gamma, const float* __restrict__ beta,
      float* __restrict__ out) {
    const int idx8 = blockIdx.x * blockDim.x + threadIdx.x;
    const int total8 = B_BATCH * N_SEQ * COUT / 8;
    if (idx8 >= total8) return;
    const int idx = idx8 * 2;
    const int o4 = (idx & (COUT / 4 - 1)) * 4;

    const float4 meanA = *reinterpret_cast<const float4*>(&g_mean[o4]);
    const float4 meanB = *reinterpret_cast<const float4*>(&g_mean[o4 + 4]);
    const float4 rstdA = *reinterpret_cast<const float4*>(&g_rstd[o4]);
    const float4 rstdB = *reinterpret_cast<const float4*>(&g_rstd[o4 + 4]);
    const float4 gaA   = *reinterpret_cast<const float4*>(&gamma[o4]);
    const float4 gaB   = *reinterpret_cast<const float4*>(&gamma[o4 + 4]);
    const float4 beA   = *reinterpret_cast<const float4*>(&beta[o4]);
    const float4 beB   = *reinterpret_cast<const float4*>(&beta[o4 + 4]);

    const size_t stride4 = (size_t)B_BATCH * N_SEQ * COUT / 4;
    const float4* yv = reinterpret_cast<const float4*>(g_y);
    float4* ov = reinterpret_cast<float4*>(out);

    float4 rA[T_STEPS], rB[T_STEPS];
#pragma unroll
    for (int t = 0; t < T_STEPS; t++) {
        const size_t off = (size_t)idx + (size_t)t * stride4;
        rA[t] = yv[off];
        rB[t] = yv[off + 1];
    }

    float vA0 = 0, vA1 = 0, vA2 = 0, vA3 = 0;
    float vB0 = 0, vB1 = 0, vB2 = 0, vB3 = 0;
#pragma unroll
    for (int t = 0; t < T_STEPS; t++) {
        const size_t off = (size_t)idx + (size_t)t * stride4;
        float4 spA, spB;
        lif_lane(rA[t].x, meanA.x, rstdA.x, gaA.x, beA.x, vA0, spA.x);
        lif_lane(rA[t].y, meanA.y, rstdA.y, gaA.y, beA.y, vA1, spA.y);
        lif_lane(rA[t].z, meanA.z, rstdA.z, gaA.z, beA.z, vA2, spA.z);
        lif_lane(rA[t].w, meanA.w, rstdA.w, gaA.w, beA.w, vA3, spA.w);
        lif_lane(rB[t].x, meanB.x, rstdB.x, gaB.x, beB.x, vB0, spB.x);
        lif_lane(rB[t].y, meanB.y, rstdB.y, gaB.y, beB.y, vB1, spB.y);
        lif_lane(rB[t].z, meanB.z, rstdB.z, gaB.z, beB.z, vB2, spB.z);
        lif_lane(rB[t].w, meanB.w, rstdB.w, gaB.w, beB.w, vB3, spB.w);
        ov[off]     = spA;
        ov[off + 1] = spB;
    }
}

// ---------------------------------------------------------------------------
extern "C" void kernel_launch(void* const* d_in, const int* in_sizes, int n_in,
                              void* d_out, int out_size) {
    const float* x     = (const float*)d_in[0];
    const float* W     = (const float*)d_in[1];
    const float* gamma = (const float*)d_in[2];
    const float* beta  = (const float*)d_in[3];
    float* out = (float*)d_out;

    dim3 wt_grid(COUT / 32, CIN / 32);
    wt_k<<<wt_grid, 256>>>(W);

    dim3 gemm_grid(COUT / BNb, M_TOTAL / BM);    // (4, 1024)
    gemm_k<<<gemm_grid, 256>>>(x);

    stats_k<<<NP2, COUT>>>();

    const int total8 = B_BATCH * N_SEQ * COUT / 8;
    lif_k<<<(total8 + 255) / 256, 256>>>(gamma, beta, out);
}

// round 16
// speedup vs baseline: 1.1435x; 1.0019x over previous
#include <cuda_runtime.h>
#include <cstdint>

// Problem constants (fixed shapes from reference setup_inputs)
#define T_STEPS 4
#define B_BATCH 32            // TB / T = 128/4
#define N_SEQ   1024
#define CIN     512
#define COUT    512
#define M_TOTAL (T_STEPS * B_BATCH * N_SEQ)   // 131072 rows

// Scratch in device globals (no allocations allowed)
__device__ float g_y[(size_t)M_TOTAL * COUT];      // 268 MB GEMM output
__device__ float g_wt[CIN][COUT];                   // W transposed: [k][o], 1 MB
#define NPART 1024
#define NP2   64
__device__ float g_psum[NPART * COUT];
__device__ float g_psq [NPART * COUT];
__device__ float g_psum2[NP2 * COUT];
__device__ float g_psq2 [NP2 * COUT];
__device__ float g_mean[COUT];
__device__ float g_rstd[COUT];
__device__ unsigned int g_ticket;                   // last-block-finalize counter

// ---------------------------------------------------------------------------
// Packed f32x2 helpers (per-lane bitwise-identical to scalar fmaf).
// ---------------------------------------------------------------------------
__device__ __forceinline__ unsigned long long pack_dup(float a) {
    unsigned long long u;
    asm("mov.b64 %0, {%1, %1};" : "=l"(u) : "f"(a));
    return u;
}
__device__ __forceinline__ void fma2(unsigned long long& acc,
                                     unsigned long long a,
                                     unsigned long long b) {
    asm("fma.rn.f32x2 %0, %1, %2, %0;" : "+l"(acc) : "l"(a), "l"(b));
}
__device__ __forceinline__ float2 unpack2(unsigned long long u) {
    float lo, hi;
    asm("mov.b64 {%0, %1}, %2;" : "=f"(lo), "=f"(hi) : "l"(u));
    return make_float2(lo, hi);
}
__device__ __forceinline__ uint32_t smem_u32(const void* p) {
    uint32_t a;
    asm("{ .reg .u64 t; cvta.to.shared.u64 t, %1; cvt.u32.u64 %0, t; }" : "=r"(a) : "l"(p));
    return a;
}
__device__ __forceinline__ void cp_async16(uint32_t dst, const void* src) {
    asm volatile("cp.async.cg.shared.global [%0], [%1], 16;" :: "r"(dst), "l"(src) : "memory");
}

// ---------------------------------------------------------------------------
// Tiled transpose: g_wt[k][o] = W[o][k]. Also resets the stats ticket
// (wt_k strictly precedes the stats kernel on the stream).
// ---------------------------------------------------------------------------
__global__ void __launch_bounds__(256)
wt_k(const float* __restrict__ W) {
    __shared__ float t[32][33];
    if (blockIdx.x == 0 && blockIdx.y == 0 && threadIdx.x == 0) g_ticket = 0u;
    const int bo = blockIdx.x * 32;
    const int bk = blockIdx.y * 32;
    const int lx = threadIdx.x & 31;
    const int ly = threadIdx.x >> 5;
#pragma unroll
    for (int i = 0; i < 4; i++)
        t[ly + 8 * i][lx] = W[(size_t)(bo + ly + 8 * i) * CIN + bk + lx];
    __syncthreads();
#pragma unroll
    for (int i = 0; i < 4; i++)
        g_wt[bk + ly + 8 * i][bo + lx] = t[lx][ly + 8 * i];
}

// ---------------------------------------------------------------------------
// SGEMM: C[m,o] = sum_k A[m,k]*W[o,k], k strictly sequential fp32 per output
// (must reproduce reference rounding; tensor-core adder trees flip spikes).
// 128x128x16 tile, 256 threads, 8x8/thread, double-buffered smem, stage loop
// manually unrolled x2 (compile-time smem addressing). Measured 93% of the
// fp32 datapath peak — structural floor under the exact-arithmetic constraint.
// BN partials fused in epilogue (deterministic tree).
// ---------------------------------------------------------------------------
#define BM 128
#define BNb 128
#define BK 16
#define SPAD 4
#define WROW (BNb + SPAD)

__global__ void __launch_bounds__(256, 2)
gemm_k(const float* __restrict__ A) {
    __shared__ float As[2][BK][BM + SPAD];
    __shared__ float Ws[2][BK][WROW];

    const int tid = threadIdx.x;
    const int lane = tid & 31;
    const int w    = tid >> 5;
    const int tx = (lane & 7) | ((w & 1) << 3);    // 0..15
    const int ty = (lane >> 3) | ((w >> 1) << 2);  // 0..15
    const int m0 = blockIdx.y * BM;
    const int n0 = blockIdx.x * BNb;

    const int ar0 = ty * 4;
    const int bc0 = tx * 4;

    const int lrow0 = tid >> 2;          // 0..63
    const int lkv   = (tid & 3) * 4;     // 0,4,8,12
    const float* Aptr0 = A + (size_t)(m0 + lrow0) * CIN + lkv;
    const size_t row64 = (size_t)64 * CIN;

    const int wk0 = tid >> 5;            // 0..7
    const int wc0 = tid & 31;
    const int wk1 = wk0 + 8;             // 8..15
    const uint32_t ws_u = smem_u32(&Ws[0][0][0]);
    const float* wsrc0 = &g_wt[wk0][n0 + wc0 * 4];
    const float* wsrc1 = &g_wt[wk1][n0 + wc0 * 4];

    unsigned long long acc[8][4];
#pragma unroll
    for (int i = 0; i < 8; i++)
#pragma unroll
        for (int j = 0; j < 4; j++) acc[i][j] = 0ULL;

    auto load_W = [&](int buf, int k0) {
        const uint32_t base = ws_u + (uint32_t)buf * (BK * WROW * 4);
        cp_async16(base + (wk0 * WROW + wc0 * 4) * 4, wsrc0 + (size_t)k0 * COUT);
        cp_async16(base + (wk1 * WROW + wc0 * 4) * 4, wsrc1 + (size_t)k0 * COUT);
        asm volatile("cp.async.commit_group;" ::: "memory");
    };
    auto store_A = [&](int buf, float4 ra0, float4 ra1) {
        As[buf][lkv + 0][lrow0] = ra0.x; As[buf][lkv + 1][lrow0] = ra0.y;
        As[buf][lkv + 2][lrow0] = ra0.z; As[buf][lkv + 3][lrow0] = ra0.w;
        As[buf][lkv + 0][lrow0 + 64] = ra1.x; As[buf][lkv + 1][lrow0 + 64] = ra1.y;
        As[buf][lkv + 2][lrow0 + 64] = ra1.z; As[buf][lkv + 3][lrow0 + 64] = ra1.w;
    };
    auto compute = [&](int buf) {
#pragma unroll
        for (int kk = 0; kk < BK; kk++) {
            float4 a0 = *reinterpret_cast<const float4*>(&As[buf][kk][ar0]);
            float4 a1 = *reinterpret_cast<const float4*>(&As[buf][kk][ar0 + 64]);
            float4 b0 = *reinterpret_cast<const float4*>(&Ws[buf][kk][bc0]);
            float4 b1 = *reinterpret_cast<const float4*>(&Ws[buf][kk][bc0 + 64]);
            unsigned long long bp[4];
            bp[0] = *reinterpret_cast<unsigned long long*>(&b0.x);
            bp[1] = *reinterpret_cast<unsigned long long*>(&b0.z);
            bp[2] = *reinterpret_cast<unsigned long long*>(&b1.x);
            bp[3] = *reinterpret_cast<unsigned long long*>(&b1.z);
            const float a[8] = {a0.x, a0.y, a0.z, a0.w, a1.x, a1.y, a1.z, a1.w};
#pragma unroll
            for (int i = 0; i < 8; i++) {
                const unsigned long long ap = pack_dup(a[i]);
#pragma unroll
                for (int jp = 0; jp < 4; jp++)
                    fma2(acc[i][jp], ap, bp[jp]);
            }
        }
    };

    // ---- prologue: stage 0 -> buffer 0
    {
        load_W(0, 0);
        float4 ra0 = *reinterpret_cast<const float4*>(Aptr0);
        float4 ra1 = *reinterpret_cast<const float4*>(Aptr0 + row64);
        store_A(0, ra0, ra1);
    }
    asm volatile("cp.async.wait_group 0;" ::: "memory");
    __syncthreads();

    // ---- main loop: 16 iterations x 2 stages, fixed buffer roles
    const int NPAIR = CIN / (2 * BK);    // 16
#pragma unroll 1
    for (int p = 0; p < NPAIR; p++) {
        const int k_odd = 2 * p * BK + BK;

        {
            load_W(1, k_odd);
            float4 ra0 = *reinterpret_cast<const float4*>(Aptr0 + k_odd);
            float4 ra1 = *reinterpret_cast<const float4*>(Aptr0 + row64 + k_odd);
            compute(0);
            store_A(1, ra0, ra1);
            asm volatile("cp.async.wait_group 0;" ::: "memory");
            __syncthreads();
        }

        if (p + 1 < NPAIR) {
            const int k_next = k_odd + BK;
            load_W(0, k_next);
            float4 ra0 = *reinterpret_cast<const float4*>(Aptr0 + k_next);
            float4 ra1 = *reinterpret_cast<const float4*>(Aptr0 + row64 + k_next);
            compute(1);
            store_A(0, ra0, ra1);
            asm volatile("cp.async.wait_group 0;" ::: "memory");
            __syncthreads();
        } else {
            compute(1);
        }
    }

    float acc_f[8][8];
#pragma unroll
    for (int i = 0; i < 8; i++)
#pragma unroll
        for (int jp = 0; jp < 4; jp++) {
            float2 v = unpack2(acc[i][jp]);
            acc_f[i][2 * jp + 0] = v.x;
            acc_f[i][2 * jp + 1] = v.y;
        }

    // ---- store C tile
#pragma unroll
    for (int ih = 0; ih < 2; ih++) {
#pragma unroll
        for (int i = 0; i < 4; i++) {
            const size_t m = (size_t)(m0 + ih * 64 + ar0 + i);
            const int ia = ih * 4 + i;
            float4 v0 = make_float4(acc_f[ia][0], acc_f[ia][1], acc_f[ia][2], acc_f[ia][3]);
            float4 v1 = make_float4(acc_f[ia][4], acc_f[ia][5], acc_f[ia][6], acc_f[ia][7]);
            *reinterpret_cast<float4*>(&g_y[m * COUT + n0 + bc0])      = v0;
            *reinterpret_cast<float4*>(&g_y[m * COUT + n0 + 64 + bc0]) = v1;
        }
    }

    // ---- fused BN partial stats (deterministic tree; reuse smem)
    __syncthreads();
    float* sred = &As[0][0][0];   // [16][128]
    float* qred = &As[1][0][0];   // [16][128]

    float s8[8], q8[8];
#pragma unroll
    for (int j = 0; j < 8; j++) { s8[j] = 0.0f; q8[j] = 0.0f; }
#pragma unroll
    for (int i = 0; i < 8; i++)
#pragma unroll
        for (int j = 0; j < 8; j++) {
            float v = acc_f[i][j];
            s8[j] += v;
            q8[j] = fmaf(v, v, q8[j]);
        }
#pragma unroll
    for (int jh = 0; jh < 2; jh++)
#pragma unroll
        for (int j = 0; j < 4; j++) {
            int c = jh * 64 + bc0 + j;
            sred[ty * 128 + c] = s8[jh * 4 + j];
            qred[ty * 128 + c] = q8[jh * 4 + j];
        }
    __syncthreads();

    if (tid < 128) {
        float s = 0.0f, q = 0.0f;
#pragma unroll
        for (int k = 0; k < 16; k++) {
            s += sred[k * 128 + tid];
            q += qred[k * 128 + tid];
        }
        g_psum[(size_t)blockIdx.y * COUT + n0 + tid] = s;
        g_psq [(size_t)blockIdx.y * COUT + n0 + tid] = q;
    }
}

// ---------------------------------------------------------------------------
// Fused BN stats: 64 blocks x 512 threads; last block (fence + ticket)
// finalizes mean/rstd in fixed index order — bitwise-deterministic.
// ---------------------------------------------------------------------------
__global__ void __launch_bounds__(COUT)
stats_k() {
    const int o = threadIdx.x;
    const int b = blockIdx.x;
    float s = 0.0f, sq = 0.0f;
#pragma unroll
    for (int i = 0; i < NPART / NP2; i++) {
        s  += g_psum[(b * (NPART / NP2) + i) * COUT + o];
        sq += g_psq [(b * (NPART / NP2) + i) * COUT + o];
    }
    g_psum2[b * COUT + o] = s;
    g_psq2 [b * COUT + o] = sq;

    __threadfence();
    __shared__ unsigned int s_last;
    __syncthreads();
    if (o == 0) {
        unsigned int t = atomicAdd(&g_ticket, 1u);
        s_last = (t == NP2 - 1) ? 1u : 0u;
    }
    __syncthreads();
    if (s_last) {
        float fs = 0.0f, fq = 0.0f;
#pragma unroll
        for (int i = 0; i < NP2; i++) {
            fs += g_psum2[i * COUT + o];
            fq += g_psq2 [i * COUT + o];
        }
        const float inv_m = 1.0f / (float)M_TOTAL;
        float mean = fs * inv_m;
        float var  = fq * inv_m - mean * mean;
        g_mean[o] = mean;
        g_rstd[o] = rsqrtf(var + 1e-5f);
    }
}

// ---------------------------------------------------------------------------
// Fused BN + multistep LIF + output store — the measured-best vec4 shape
// (R9/R10: 4 channels/thread, regs~40, occ~59%, 74.3us, DRAM 82%).
// Per-lane math identical to scalar -> bitwise-identical spikes.
// ---------------------------------------------------------------------------
__global__ void __launch_bounds__(256)
lif_k(const float* __restrict__ gamma, const float* __restrict__ beta,
      float* __restrict__ out) {
    const int idx = blockIdx.x * blockDim.x + threadIdx.x;   // vec4 index
    const int total4 = B_BATCH * N_SEQ * COUT / 4;
    if (idx >= total4) return;
    const int o4 = (idx & (COUT / 4 - 1)) * 4;               // channel base

    const float4 mean = *reinterpret_cast<const float4*>(&g_mean[o4]);
    const float4 rstd = *reinterpret_cast<const float4*>(&g_rstd[o4]);
    const float4 ga   = *reinterpret_cast<const float4*>(&gamma[o4]);
    const float4 be   = *reinterpret_cast<const float4*>(&beta[o4]);

    const size_t stride4 = (size_t)B_BATCH * N_SEQ * COUT / 4;
    const size_t base = (size_t)idx;
    const float4* yv = reinterpret_cast<const float4*>(g_y);
    float4* ov = reinterpret_cast<float4*>(out);

    float v0 = 0.0f, v1 = 0.0f, v2 = 0.0f, v3 = 0.0f;
#pragma unroll
    for (int t = 0; t < T_STEPS; t++) {
        const size_t off = base + (size_t)t * stride4;
        float4 raw = yv[off];
        float4 sp;
        {   float xt = (raw.x - mean.x) * rstd.x; xt = xt * ga.x + be.x;
            v0 = v0 + (xt - v0) * 0.5f;
            sp.x = (v0 >= 1.0f) ? 1.0f : 0.0f;
            v0 = v0 * (1.0f - sp.x); }
        {   float xt = (raw.y - mean.y) * rstd.y; xt = xt * ga.y + be.y;
            v1 = v1 + (xt - v1) * 0.5f;
            sp.y = (v1 >= 1.0f) ? 1.0f : 0.0f;
            v1 = v1 * (1.0f - sp.y); }
        {   float xt = (raw.z - mean.z) * rstd.z; xt = xt * ga.z + be.z;
            v2 = v2 + (xt - v2) * 0.5f;
            sp.z = (v2 >= 1.0f) ? 1.0f : 0.0f;
            v2 = v2 * (1.0f - sp.z); }
        {   float xt = (raw.w - mean.w) * rstd.w; xt = xt * ga.w + be.w;
            v3 = v3 + (xt - v3) * 0.5f;
            sp.w = (v3 >= 1.0f) ? 1.0f : 0.0f;
            v3 = v3 * (1.0f - sp.w); }
        ov[off] = sp;
    }
}

// ---------------------------------------------------------------------------
extern "C" void kernel_launch(void* const* d_in, const int* in_sizes, int n_in,
                              void* d_out, int out_size) {
    const float* x     = (const float*)d_in[0];
    const float* W     = (const float*)d_in[1];
    const float* gamma = (const float*)d_in[2];
    const float* beta  = (const float*)d_in[3];
    float* out = (float*)d_out;

    dim3 wt_grid(COUT / 32, CIN / 32);
    wt_k<<<wt_grid, 256>>>(W);

    dim3 gemm_grid(COUT / BNb, M_TOTAL / BM);    // (4, 1024)
    gemm_k<<<gemm_grid, 256>>>(x);

    stats_k<<<NP2, COUT>>>();

    const int total4 = B_BATCH * N_SEQ * COUT / 4;   // 4.19M vec4
    lif_k<<<(total4 + 255) / 256, 256>>>(gamma, beta, out);
}